// round 13
// baseline (speedup 1.0000x reference)
#include <cuda_runtime.h>
#include <math.h>
#include <limits.h>

// Problem constants
#define NTOK 50176            // 16 * 56 * 56
#define CDIM 96
#define QKVDIM 288
#define HIDDIM 384
#define LITDIM 768
#define NCLAUSE 128
#define NWIN 1024             // 16 * 8 * 8
#define IMGHW 56
#define LNEPS 1e-5f

// ---------------- scratch (static device arrays; no allocation) -------------
__device__ float g_mu [(size_t)NTOK];
__device__ float g_rs [(size_t)NTOK];
__device__ float g_qkv[(size_t)NTOK * QKVDIM];
__device__ float g_ao [(size_t)NTOK * CDIM];
__device__ float g_x1 [(size_t)NTOK * CDIM];
__device__ float g_w  [(size_t)NTOK * CDIM];
__device__ float g_ll [(size_t)NTOK * LITDIM];
__device__ float g_cl [(size_t)NTOK * NCLAUSE];
__device__ float g_qwh[QKVDIM * CDIM];   // tf32-hi of qkv_w
__device__ float g_qwl[QKVDIM * CDIM];   // tf32-lo of qkv_w
__device__ float g_pwh[CDIM * CDIM];     // tf32-hi of proj_w
__device__ float g_pwl[CDIM * CDIM];     // tf32-lo of proj_w
__device__ int   g_skip;     // 1 => TM-FFN branch provably ~0, take fast path

// ---------------- helpers ---------------------------------------------------
__device__ __forceinline__ float warp_sum(float v) {
#pragma unroll
    for (int o = 16; o > 0; o >>= 1) v += __shfl_xor_sync(0xffffffffu, v, o);
    return v;
}

__device__ __forceinline__ unsigned f2tf32(float x) {
    unsigned r;
    asm("cvt.rna.tf32.f32 %0, %1;" : "=r"(r) : "f"(x));
    return r;
}

// d += A(16x8) * B(8x8), tf32 operands, f32 accum. Standard m16n8k8 fragments.
__device__ __forceinline__ void mma_tf32(float* d, const unsigned* a,
                                         const unsigned* b) {
    asm("mma.sync.aligned.m16n8k8.row.col.f32.tf32.tf32.f32 "
        "{%0,%1,%2,%3}, {%4,%5,%6,%7}, {%8,%9}, {%0,%1,%2,%3};"
        : "+f"(d[0]), "+f"(d[1]), "+f"(d[2]), "+f"(d[3])
        : "r"(a[0]), "r"(a[1]), "r"(a[2]), "r"(a[3]), "r"(b[0]), "r"(b[1]));
}

#define SPLIT2(hi, lo, x) { hi = f2tf32(x); lo = f2tf32((x) - __uint_as_float(hi)); }

// ---------------- weight pre-split (one tiny launch) -------------------------
__global__ __launch_bounds__(256) void splitw_kernel(
    const float* __restrict__ qkv_w, const float* __restrict__ proj_w,
    float* __restrict__ qwh, float* __restrict__ qwl,
    float* __restrict__ pwh, float* __restrict__ pwl)
{
    int i = blockIdx.x * 256 + threadIdx.x;
    if (i < QKVDIM * CDIM) {
        float v = qkv_w[i];
        unsigned h = f2tf32(v);
        qwh[i] = __uint_as_float(h);
        qwl[i] = __uint_as_float(f2tf32(v - __uint_as_float(h)));
    }
    if (i < CDIM * CDIM) {
        float v = proj_w[i];
        unsigned h = f2tf32(v);
        pwh[i] = __uint_as_float(h);
        pwl[i] = __uint_as_float(f2tf32(v - __uint_as_float(h)));
    }
}

// ---------------- guard: is the clause branch provably negligible? ----------
// Any literal pair (j, j+384) with BOTH mask bits set contributes
// log(max(y,eps)) + log(max(1-y,eps)) <= log(1/4) to the clause exponent S,
// so |logits| <= NCLAUSE * max|tm_out| * exp(-1.386 * min_c n_both(c)).
// Bound < 1e-25 => replacing logits by 0 perturbs output < 1e-25: fast path.
__global__ __launch_bounds__(1024) void guard_kernel(
    const float* __restrict__ tm_inc, const float* __restrict__ tm_out,
    int* __restrict__ flag)
{
    __shared__ int   cnt[1024];
    __shared__ int   csum[NCLAUSE];
    __shared__ float mxs[1024];
    int t = threadIdx.x;
    int c = t >> 3, sub = t & 7;      // 8 threads per clause, 48 pairs each
    const float4* rowA = (const float4*)(tm_inc + (size_t)c * LITDIM);
    const float4* rowB = (const float4*)(tm_inc + (size_t)c * LITDIM + HIDDIM);
    int cn = 0;
    int base = sub * 12;              // 12 float4 = 48 floats
#pragma unroll
    for (int q = 0; q < 12; q++) {
        float4 a = rowA[base + q];
        float4 b = rowB[base + q];
        cn += (a.x > 0.0f && b.x > 0.0f) ? 1 : 0;
        cn += (a.y > 0.0f && b.y > 0.0f) ? 1 : 0;
        cn += (a.z > 0.0f && b.z > 0.0f) ? 1 : 0;
        cn += (a.w > 0.0f && b.w > 0.0f) ? 1 : 0;
    }
    cnt[t] = cn;
    float m = 0.0f;
    const float4* to4 = (const float4*)tm_out;   // 12288 floats = 3072 float4
#pragma unroll
    for (int q = 0; q < 3; q++) {
        float4 v = to4[t + q * 1024];
        m = fmaxf(m, fmaxf(fmaxf(fabsf(v.x), fabsf(v.y)),
                           fmaxf(fabsf(v.z), fabsf(v.w))));
    }
    mxs[t] = m;
    __syncthreads();
    if (t < NCLAUSE) {
        int s = 0;
#pragma unroll
        for (int i = 0; i < 8; i++) s += cnt[t * 8 + i];
        csum[t] = s;
    }
    __syncthreads();
    if (t == 0) {
        int mn = INT_MAX;
        for (int i = 0; i < NCLAUSE; i++) mn = (csum[i] < mn) ? csum[i] : mn;
        float M = 0.0f;
        for (int i = 0; i < 1024; i++) M = fmaxf(M, mxs[i]);
        float logbound = logf((float)NCLAUSE * M + 1e-30f) - 1.3862944f * (float)mn;
        flag[0] = (logbound < -57.6f) ? 1 : 0;   // e^-57.6 ~ 1e-25
    }
}

// ---------------- LN1 stats only (mean + rstd per token) ---------------------
__global__ __launch_bounds__(256) void ln1_stats(
    const float* __restrict__ x, float* __restrict__ mu, float* __restrict__ rs)
{
    int warp = (blockIdx.x * blockDim.x + threadIdx.x) >> 5;
    int lane = threadIdx.x & 31;
    if (warp >= NTOK) return;
    size_t base = (size_t)warp * CDIM;
    float v0 = x[base + lane];
    float v1 = x[base + lane + 32];
    float v2 = x[base + lane + 64];
    float mean = warp_sum(v0 + v1 + v2) * (1.0f / CDIM);
    float d0 = v0 - mean, d1 = v1 - mean, d2 = v2 - mean;
    float var = warp_sum(d0 * d0 + d1 * d1 + d2 * d2) * (1.0f / CDIM);
    if (lane == 0) {
        mu[warp] = mean;
        rs[warp] = rsqrtf(var + LNEPS);
    }
}

// double layernorm: w = LN(LN(x1, g2, b2), fg, fb); early-exit on fast path
__global__ __launch_bounds__(256) void ln2_kernel(
    const float* __restrict__ x, const float* __restrict__ g2,
    const float* __restrict__ b2, const float* __restrict__ fg,
    const float* __restrict__ fb, float* __restrict__ y,
    const int* __restrict__ flag)
{
    if (flag[0]) return;
    int warp = (blockIdx.x * blockDim.x + threadIdx.x) >> 5;
    int lane = threadIdx.x & 31;
    if (warp >= NTOK) return;
    size_t base = (size_t)warp * CDIM;
    float v0 = x[base + lane];
    float v1 = x[base + lane + 32];
    float v2 = x[base + lane + 64];
    float mean = warp_sum(v0 + v1 + v2) * (1.0f / CDIM);
    float d0 = v0 - mean, d1 = v1 - mean, d2 = v2 - mean;
    float var = warp_sum(d0 * d0 + d1 * d1 + d2 * d2) * (1.0f / CDIM);
    float rsv = rsqrtf(var + LNEPS);
    float z0 = d0 * rsv * g2[lane]      + b2[lane];
    float z1 = d1 * rsv * g2[lane + 32] + b2[lane + 32];
    float z2 = d2 * rsv * g2[lane + 64] + b2[lane + 64];
    float m2 = warp_sum(z0 + z1 + z2) * (1.0f / CDIM);
    float e0 = z0 - m2, e1 = z1 - m2, e2 = z2 - m2;
    float var2 = warp_sum(e0 * e0 + e1 * e1 + e2 * e2) * (1.0f / CDIM);
    float rs2 = rsqrtf(var2 + LNEPS);
    y[base + lane]      = e0 * rs2 * fg[lane]      + fb[lane];
    y[base + lane + 32] = e1 * rs2 * fg[lane + 32] + fb[lane + 32];
    y[base + lane + 64] = e2 * rs2 * fg[lane + 64] + fb[lane + 64];
}

// ---------------- TF32 tensor-core GEMM v2 (pre-split B weights) -------------
// C[M x N] = A[M x 96] @ B^T (+bias); Bhi/Blo are pre-split N x 96 row-major.
// BM=64, BN=96, 8 warps, warp tile 16x48. In-loop cvt only for A (halved).
// LNA: A element = (x - mu[m]) * rs[m] * gamma[k] + beta[k] applied at load.
// MODE 1 (qkv): C = acc + bias[n]
// MODE 2 (proj): full path -> C = ex1 + acc + bias
//                fast path -> Cfast = ex1 + acc + bias + (1-sigmoid(gate))*0.5
#define TC_LDA 100   // row pitch (mod 32 == 4 -> conflict-free frag loads)
#define TC2_SMEM ((64 * TC_LDA + 2 * 96 * TC_LDA) * 4)

template<int MODE, bool LNA>
__global__ __launch_bounds__(256, 2) void gemmtc2_k(
    const float* __restrict__ A, const float* __restrict__ Bhi,
    const float* __restrict__ Blo,
    const float* __restrict__ bias, const float* __restrict__ ex1,
    float* __restrict__ C, int ldc,
    const float* __restrict__ MU, const float* __restrict__ RS,
    const float* __restrict__ LNG, const float* __restrict__ LNB,
    float* __restrict__ Cfast, const float* __restrict__ gatep,
    const int* __restrict__ flag)
{
    extern __shared__ float sm[];
    float* As = sm;                    // [64][TC_LDA]
    float* Bh = sm + 64 * TC_LDA;      // [96][TC_LDA]
    float* Bl = Bh + 96 * TC_LDA;      // [96][TC_LDA]
    __shared__ float gsm[CDIM], bsm[CDIM], bias_sm[96];

    int tid  = threadIdx.x;
    int warp = tid >> 5;
    int lane = tid & 31;
    int gid  = lane >> 2;      // 0..7
    int tig  = lane & 3;       // 0..3
    int m0 = blockIdx.x * 64;
    int n0 = blockIdx.y * 96;
    int mw = (warp & 3) * 16;  // warp m offset
    int nw = (warp >> 2) * 48; // warp n offset

    if (tid < 96) {
        bias_sm[tid] = bias[n0 + tid];
        if (LNA) { gsm[tid] = LNG[tid]; bsm[tid] = LNB[tid]; }
    }

    // load A tile (64 x 96), LN fused; 4 threads per row, 24 cols each
    {
        int r  = tid >> 2;
        int cb = (tid & 3) * 24;
        const float* ap = A + (size_t)(m0 + r) * CDIM + cb;
        float* as = As + r * TC_LDA + cb;
        if (LNA) {
            __syncthreads();   // gsm/bsm ready
            float muv = MU[m0 + r], rsv = RS[m0 + r];
#pragma unroll
            for (int q = 0; q < 6; q++) {
                float4 v = *(const float4*)(ap + q * 4);
                int k = cb + q * 4;
                v.x = (v.x - muv) * rsv * gsm[k]     + bsm[k];
                v.y = (v.y - muv) * rsv * gsm[k + 1] + bsm[k + 1];
                v.z = (v.z - muv) * rsv * gsm[k + 2] + bsm[k + 2];
                v.w = (v.w - muv) * rsv * gsm[k + 3] + bsm[k + 3];
                *(float4*)(as + q * 4) = v;
            }
        } else {
#pragma unroll
            for (int q = 0; q < 6; q++)
                *(float4*)(as + q * 4) = *(const float4*)(ap + q * 4);
        }
    }
    // load pre-split B tiles (96 x 96 each): threads 0..191, 2 per row
    if (tid < 192) {
        int r  = tid >> 1;
        int cb = (tid & 1) * 48;
        const float* bph = Bhi + (size_t)(n0 + r) * CDIM + cb;
        const float* bpl = Blo + (size_t)(n0 + r) * CDIM + cb;
        float* bsh = Bh + r * TC_LDA + cb;
        float* bsl = Bl + r * TC_LDA + cb;
#pragma unroll
        for (int q = 0; q < 12; q++) {
            *(float4*)(bsh + q * 4) = *(const float4*)(bph + q * 4);
            *(float4*)(bsl + q * 4) = *(const float4*)(bpl + q * 4);
        }
    }
    __syncthreads();

    float acc[6][4];
#pragma unroll
    for (int nt = 0; nt < 6; nt++)
#pragma unroll
        for (int i = 0; i < 4; i++) acc[nt][i] = 0.0f;

#pragma unroll 2
    for (int kk = 0; kk < 96; kk += 8) {
        unsigned bh[6][2], bl6[6][2];
#pragma unroll
        for (int nt = 0; nt < 6; nt++) {
            int rb = (nw + nt * 8 + gid) * TC_LDA + kk + tig;
            bh[nt][0]  = __float_as_uint(Bh[rb]);
            bh[nt][1]  = __float_as_uint(Bh[rb + 4]);
            bl6[nt][0] = __float_as_uint(Bl[rb]);
            bl6[nt][1] = __float_as_uint(Bl[rb + 4]);
        }
        unsigned ah[4], al[4];
        {
            int rb = (mw + gid) * TC_LDA + kk + tig;
            float a0 = As[rb];
            float a1 = As[rb + 8 * TC_LDA];
            float a2 = As[rb + 4];
            float a3 = As[rb + 8 * TC_LDA + 4];
            SPLIT2(ah[0], al[0], a0);
            SPLIT2(ah[1], al[1], a1);
            SPLIT2(ah[2], al[2], a2);
            SPLIT2(ah[3], al[3], a3);
        }
#pragma unroll
        for (int nt = 0; nt < 6; nt++) {
            mma_tf32(acc[nt], ah, bh[nt]);
            mma_tf32(acc[nt], al, bh[nt]);
            mma_tf32(acc[nt], ah, bl6[nt]);
        }
    }

    // epilogue
    float add = 0.0f;
    float* dst = C;
    if (MODE == 2) {
        if (flag[0]) {
            float gte = 1.0f / (1.0f + expf(-gatep[0]));
            add = (1.0f - gte) * 0.5f;
            dst = Cfast;
        }
    }
#pragma unroll
    for (int nt = 0; nt < 6; nt++) {
        int m1 = m0 + mw + gid;
        int nc = nw + nt * 8 + tig * 2;      // col within 96-slice
        int n1 = n0 + nc;
        float b0 = bias_sm[nc], b1 = bias_sm[nc + 1];
        float* d = acc[nt];
        if (MODE == 1) {
            float2 v0 = {d[0] + b0, d[1] + b1};
            float2 v1 = {d[2] + b0, d[3] + b1};
            *(float2*)&C[(size_t)m1 * ldc + n1] = v0;
            *(float2*)&C[(size_t)(m1 + 8) * ldc + n1] = v1;
        } else {
            float2 e0 = *(const float2*)&ex1[(size_t)m1 * CDIM + n1];
            float2 e1 = *(const float2*)&ex1[(size_t)(m1 + 8) * CDIM + n1];
            float2 v0 = {e0.x + d[0] + b0 + add, e0.y + d[1] + b1 + add};
            float2 v1 = {e1.x + d[2] + b0 + add, e1.y + d[3] + b1 + add};
            *(float2*)&dst[(size_t)m1 * ldc + n1] = v0;
            *(float2*)&dst[(size_t)(m1 + 8) * ldc + n1] = v1;
        }
    }
}

// ---------------- fp32 tiled GEMM, 128x128x16 (modes 3,4,5; full path only) --
// SKIP=1: early-exit whole kernel when flag set.
template<int MODE, bool BTRANS, bool BMASK, int SKIP>
__global__ __launch_bounds__(256, 2) void gemm2_k(
    const float* __restrict__ A, const float* __restrict__ B,
    const float* __restrict__ bias, const float* __restrict__ ex1,
    const float* __restrict__ ex2, float* __restrict__ C,
    int M, int N, int K, int ldc, const int* __restrict__ flag)
{
    const int BM = 128, BN = 128, BK = 16;

    int tid = threadIdx.x;
    int m0 = blockIdx.x * BM;
    int n0 = blockIdx.y * BN;
    int tx = tid & 15;
    int ty = tid >> 4;

    if (SKIP == 1) {
        if (flag[0]) return;
    }

    __shared__ __align__(16) float As[2][BK][BM + 4];
    __shared__ __align__(16) float Bs[2][BK][BN + 4];

    int lr = tid >> 1;
    int lk = (tid & 1) * 8;
    int bk = tid >> 4;
    int bn = (tid & 15) * 8;

    float acc[8][8];
#pragma unroll
    for (int i = 0; i < 8; i++)
#pragma unroll
        for (int j = 0; j < 8; j++) acc[i][j] = 0.0f;

    float ldA[8], ldB[8];
    int KT = K / BK;

#define GEMM_LOAD(kt)                                                        \
    {                                                                        \
        const float* ap = A + (size_t)(m0 + lr) * K + (kt) * BK + lk;        \
        *(float4*)&ldA[0] = *(const float4*)ap;                              \
        *(float4*)&ldA[4] = *(const float4*)(ap + 4);                        \
        if (!BTRANS) {                                                       \
            int n = n0 + lr;                                                 \
            if (n < N) {                                                     \
                const float* bp = B + (size_t)n * K + (kt) * BK + lk;        \
                *(float4*)&ldB[0] = *(const float4*)bp;                      \
                *(float4*)&ldB[4] = *(const float4*)(bp + 4);                \
            } else {                                                         \
                _Pragma("unroll")                                            \
                for (int j = 0; j < 8; j++) ldB[j] = 0.0f;                   \
            }                                                                \
            if (BMASK) {                                                     \
                _Pragma("unroll")                                            \
                for (int j = 0; j < 8; j++)                                  \
                    ldB[j] = (ldB[j] > 0.0f) ? 1.0f : 0.0f;                  \
            }                                                                \
        } else {                                                             \
            _Pragma("unroll")                                                \
            for (int j = 0; j < 8; j++) {                                    \
                int n = n0 + bn + j;                                         \
                ldB[j] = (n < N)                                             \
                    ? B[(size_t)((kt) * BK + bk) * N + n] : 0.0f;            \
            }                                                                \
        }                                                                    \
    }

#define GEMM_STS(bsel)                                                       \
    {                                                                        \
        _Pragma("unroll")                                                    \
        for (int j = 0; j < 8; j++) As[bsel][lk + j][lr] = ldA[j];           \
        if (!BTRANS) {                                                       \
            _Pragma("unroll")                                                \
            for (int j = 0; j < 8; j++) Bs[bsel][lk + j][lr] = ldB[j];       \
        } else {                                                             \
            _Pragma("unroll")                                                \
            for (int j = 0; j < 8; j++) Bs[bsel][bk][bn + j] = ldB[j];       \
        }                                                                    \
    }

    GEMM_LOAD(0);
    GEMM_STS(0);
    __syncthreads();

    int buf = 0;
    for (int kt = 0; kt < KT; kt++) {
        if (kt + 1 < KT) GEMM_LOAD(kt + 1);
#pragma unroll
        for (int k = 0; k < BK; k++) {
            float4 a0 = *(const float4*)&As[buf][k][ty * 4];
            float4 a1 = *(const float4*)&As[buf][k][ty * 4 + 64];
            float4 b0 = *(const float4*)&Bs[buf][k][tx * 4];
            float4 b1 = *(const float4*)&Bs[buf][k][tx * 4 + 64];
            float a[8] = {a0.x, a0.y, a0.z, a0.w, a1.x, a1.y, a1.z, a1.w};
            float b[8] = {b0.x, b0.y, b0.z, b0.w, b1.x, b1.y, b1.z, b1.w};
#pragma unroll
            for (int i = 0; i < 8; i++)
#pragma unroll
                for (int j = 0; j < 8; j++) acc[i][j] += a[i] * b[j];
        }
        if (kt + 1 < KT) {
            GEMM_STS(buf ^ 1);
            __syncthreads();
        }
        buf ^= 1;
    }

    float gte = 0.0f;
    if (MODE == 5) gte = 1.0f / (1.0f + expf(-ex2[0]));
#pragma unroll
    for (int i = 0; i < 8; i++) {
        int m = m0 + ty * 4 + (i < 4 ? i : 60 + i);
#pragma unroll
        for (int j = 0; j < 8; j++) {
            int n = n0 + tx * 4 + (j < 4 ? j : 60 + j);
            if (n >= N) continue;
            float v = acc[i][j];
            if (MODE == 3) {
                float y = 1.0f / (1.0f + expf(-(v + bias[n])));
                C[(size_t)m * LITDIM + n]          = logf(fmaxf(y, 1e-6f));
                C[(size_t)m * LITDIM + HIDDIM + n] = logf(fmaxf(1.0f - y, 1e-6f));
            } else if (MODE == 4) {
                C[(size_t)m * ldc + n] = expf(v);
            } else if (MODE == 5) {
                float s = 1.0f / (1.0f + expf(-v));
                C[(size_t)m * ldc + n] = ex1[(size_t)m * CDIM + n] + gte * v + (1.0f - gte) * s;
            }
        }
    }
#undef GEMM_LOAD
#undef GEMM_STS
}

// ---------------- windowed attention, tensor cores + pre-split K/V -----------
// grid (NWIN, 3), block 128 (4 warps). K and V fragments pre-split to tf32
// hi/lo in smem at load (1x per element instead of 1x per warp = 4x fewer cvt).
// Dynamic smem layout (floats):
//   qs   [64][36]   (fp32 Q, rows 49..63 zero)
//   ksh  [56][36]   (tf32-hi of K, rows 49..55 zero)
//   ksl  [56][36]
//   vth  [32][60]   (tf32-hi of V^T, cols 49..55 zero)
//   vtl  [32][60]
//   ps   [64][60]   (scores / probs; cols 49..59 zeroed upfront)
#define AT_SMEM ((64*36 + 2*56*36 + 2*32*60 + 64*60) * 4)

__global__ __launch_bounds__(128) void attn3_kernel(
    const float* __restrict__ qkv, float* __restrict__ ao)
{
    extern __shared__ float smf[];
    float* qs  = smf;                  // 64*36
    float* ksh = qs  + 64 * 36;        // 56*36
    float* ksl = ksh + 56 * 36;
    float* vth = ksl + 56 * 36;        // 32*60
    float* vtl = vth + 32 * 60;
    float* ps  = vtl + 32 * 60;        // 64*60
    __shared__ int ltab[49];
    __shared__ int otab[49];

    int w  = blockIdx.x;
    int h  = blockIdx.y;
    int b  = w >> 6;
    int wh = (w >> 3) & 7;
    int ww = w & 7;
    int tid  = threadIdx.x;
    int warp = tid >> 5;
    int lane = tid & 31;
    int gid  = lane >> 2;     // 0..7
    int tig  = lane & 3;      // 0..3

    if (tid < 49) {
        int th = tid / 7, tw = tid % 7;
        int r = (wh * 7 + th + 3) % IMGHW;
        int c = (ww * 7 + tw + 3) % IMGHW;
        ltab[tid] = b * (IMGHW * IMGHW) + r * IMGHW + c;
        int ro = wh * 7 + (th + 3) % 7;          // intra-window inverse roll
        int co = ww * 7 + (tw + 3) % 7;
        otab[tid] = b * (IMGHW * IMGHW) + ro * IMGHW + co;
    }
    // zero pads
    for (int i = tid; i < 15 * 36; i += 128) qs[(49 + i / 36) * 36 + i % 36] = 0.0f;
    for (int i = tid; i < 7 * 36; i += 128) {
        ksh[(49 + i / 36) * 36 + i % 36] = 0.0f;
        ksl[(49 + i / 36) * 36 + i % 36] = 0.0f;
    }
    for (int i = tid; i < 32 * 11; i += 128) {
        vth[(i / 11) * 60 + 49 + i % 11] = 0.0f;
        vtl[(i / 11) * 60 + 49 + i % 11] = 0.0f;
    }
    for (int i = tid; i < 64 * 11; i += 128)    // ps pad cols 49..59 all rows
        ps[(i / 11) * 60 + 49 + i % 11] = 0.0f;
    __syncthreads();

    // load q (fp32) and pre-split k, v(transposed) into hi/lo
    for (int i = tid; i < 49 * 8; i += 128) {
        int t = i >> 3, dq = (i & 7) * 4;
        const float* base = qkv + (size_t)ltab[t] * QKVDIM + h * 32 + dq;
        *(float4*)&qs[t * 36 + dq] = *(const float4*)base;
        float4 kv = *(const float4*)(base + 96);
        float4 vv = *(const float4*)(base + 192);
        unsigned hh, ll;
        SPLIT2(hh, ll, kv.x); ksh[t*36+dq]   = __uint_as_float(hh); ksl[t*36+dq]   = __uint_as_float(ll);
        SPLIT2(hh, ll, kv.y); ksh[t*36+dq+1] = __uint_as_float(hh); ksl[t*36+dq+1] = __uint_as_float(ll);
        SPLIT2(hh, ll, kv.z); ksh[t*36+dq+2] = __uint_as_float(hh); ksl[t*36+dq+2] = __uint_as_float(ll);
        SPLIT2(hh, ll, kv.w); ksh[t*36+dq+3] = __uint_as_float(hh); ksl[t*36+dq+3] = __uint_as_float(ll);
        SPLIT2(hh, ll, vv.x); vth[(dq)*60+t]   = __uint_as_float(hh); vtl[(dq)*60+t]   = __uint_as_float(ll);
        SPLIT2(hh, ll, vv.y); vth[(dq+1)*60+t] = __uint_as_float(hh); vtl[(dq+1)*60+t] = __uint_as_float(ll);
        SPLIT2(hh, ll, vv.z); vth[(dq+2)*60+t] = __uint_as_float(hh); vtl[(dq+2)*60+t] = __uint_as_float(ll);
        SPLIT2(hh, ll, vv.w); vth[(dq+3)*60+t] = __uint_as_float(hh); vtl[(dq+3)*60+t] = __uint_as_float(ll);
    }
    __syncthreads();

    const float scale = 0.17677669529663687f;  // 1/sqrt(32)

    // ---- scores: warp = m-tile (16 rows); 7 n-tiles x 4 k-tiles x 3 mma ----
    {
        int mrow = warp * 16 + gid;
        unsigned ah[4][4], al[4][4];
#pragma unroll
        for (int kt = 0; kt < 4; kt++) {
            int kc = kt * 8 + tig;
            float a0 = qs[mrow * 36 + kc];
            float a1 = qs[(mrow + 8) * 36 + kc];
            float a2 = qs[mrow * 36 + kc + 4];
            float a3 = qs[(mrow + 8) * 36 + kc + 4];
            SPLIT2(ah[kt][0], al[kt][0], a0);
            SPLIT2(ah[kt][1], al[kt][1], a1);
            SPLIT2(ah[kt][2], al[kt][2], a2);
            SPLIT2(ah[kt][3], al[kt][3], a3);
        }
#pragma unroll
        for (int nt = 0; nt < 7; nt++) {
            unsigned bh[4][2], bl[4][2];
#pragma unroll
            for (int kt = 0; kt < 4; kt++) {
                int rb = (nt * 8 + gid) * 36 + kt * 8 + tig;
                bh[kt][0] = __float_as_uint(ksh[rb]);
                bh[kt][1] = __float_as_uint(ksh[rb + 4]);
                bl[kt][0] = __float_as_uint(ksl[rb]);
                bl[kt][1] = __float_as_uint(ksl[rb + 4]);
            }
            float acc[4] = {0.0f, 0.0f, 0.0f, 0.0f};
#pragma unroll
            for (int kt = 0; kt < 4; kt++) {
                mma_tf32(acc, ah[kt], bh[kt]);
                mma_tf32(acc, al[kt], bh[kt]);
                mma_tf32(acc, ah[kt], bl[kt]);
            }
            int c = nt * 8 + tig * 2;
            if (c < 49) {
                ps[mrow * 60 + c]       = acc[0] * scale;
                ps[(mrow + 8) * 60 + c] = acc[2] * scale;
            }
            if (c + 1 < 49) {
                ps[mrow * 60 + c + 1]       = acc[1] * scale;
                ps[(mrow + 8) * 60 + c + 1] = acc[3] * scale;
            }
        }
    }
    __syncthreads();

    // softmax: 2 threads per row (rows 0..48); pad cols already zero
    if (tid < 98) {
        int row = tid >> 1, half = tid & 1;
        int c0 = half ? 25 : 0;
        int c1 = half ? 49 : 25;
        unsigned mask = (tid < 96) ? 0xffffffffu : 0x3u;
        float mx = -1e30f;
        for (int j = c0; j < c1; j++) mx = fmaxf(mx, ps[row * 60 + j]);
        mx = fmaxf(mx, __shfl_xor_sync(mask, mx, 1));
        float sum = 0.0f;
        for (int j = c0; j < c1; j++) {
            float e = expf(ps[row * 60 + j] - mx);
            ps[row * 60 + j] = e;
            sum += e;
        }
        sum += __shfl_xor_sync(mask, sum, 1);
        float inv = 1.0f / sum;
        for (int j = c0; j < c1; j++) ps[row * 60 + j] *= inv;
    }
    __syncthreads();

    // ---- AV: O(64x32) = P @ V; warp = m-tile; 4 n-tiles x 7 k-tiles x 3 ----
    {
        int mrow = warp * 16 + gid;
        unsigned ah[7][4], al[7][4];
#pragma unroll
        for (int kt = 0; kt < 7; kt++) {
            int kc = kt * 8 + tig;
            float a0 = ps[mrow * 60 + kc];
            float a1 = ps[(mrow + 8) * 60 + kc];
            float a2 = ps[mrow * 60 + kc + 4];
            float a3 = ps[(mrow + 8) * 60 + kc + 4];
            SPLIT2(ah[kt][0], al[kt][0], a0);
            SPLIT2(ah[kt][1], al[kt][1], a1);
            SPLIT2(ah[kt][2], al[kt][2], a2);
            SPLIT2(ah[kt][3], al[kt][3], a3);
        }
#pragma unroll
        for (int nt = 0; nt < 4; nt++) {
            unsigned bh[7][2], bl[7][2];
#pragma unroll
            for (int kt = 0; kt < 7; kt++) {
                int rb = (nt * 8 + gid) * 60 + kt * 8 + tig;
                bh[kt][0] = __float_as_uint(vth[rb]);
                bh[kt][1] = __float_as_uint(vth[rb + 4]);
                bl[kt][0] = __float_as_uint(vtl[rb]);
                bl[kt][1] = __float_as_uint(vtl[rb + 4]);
            }
            float acc[4] = {0.0f, 0.0f, 0.0f, 0.0f};
#pragma unroll
            for (int kt = 0; kt < 7; kt++) {
                mma_tf32(acc, ah[kt], bh[kt]);
                mma_tf32(acc, al[kt], bh[kt]);
                mma_tf32(acc, ah[kt], bl[kt]);
            }
            int d = nt * 8 + tig * 2;
            int t0 = mrow, t1 = mrow + 8;
            if (t0 < 49) {
                float2 o = {acc[0], acc[1]};
                *(float2*)&ao[(size_t)otab[t0] * CDIM + h * 32 + d] = o;
            }
            if (t1 < 49) {
                float2 o = {acc[2], acc[3]};
                *(float2*)&ao[(size_t)otab[t1] * CDIM + h * 32 + d] = o;
            }
        }
    }
}

// ---------------- host launcher ----------------------------------------------
extern "C" void kernel_launch(void* const* d_in, const int* in_sizes, int n_in,
                              void* d_out, int out_size)
{
    const float* x       = (const float*)d_in[0];
    const float* n1g     = (const float*)d_in[1];
    const float* n1b     = (const float*)d_in[2];
    const float* qkv_w   = (const float*)d_in[3];
    const float* qkv_b   = (const float*)d_in[4];
    const float* proj_w  = (const float*)d_in[5];
    const float* proj_b  = (const float*)d_in[6];
    const float* n2g     = (const float*)d_in[7];
    const float* n2b     = (const float*)d_in[8];
    const float* fng     = (const float*)d_in[9];
    const float* fnb     = (const float*)d_in[10];
    const float* pin_w   = (const float*)d_in[11];
    const float* pin_b   = (const float*)d_in[12];
    const float* tm_inc  = (const float*)d_in[13];
    const float* tm_out  = (const float*)d_in[14];
    const float* gate    = (const float*)d_in[15];
    float* out           = (float*)d_out;

    float *p_mu, *p_rs, *p_qkv, *p_ao, *p_x1, *p_w, *p_ll, *p_cl;
    float *p_qwh, *p_qwl, *p_pwh, *p_pwl;
    int* p_skip;
    cudaGetSymbolAddress((void**)&p_mu,  g_mu);
    cudaGetSymbolAddress((void**)&p_rs,  g_rs);
    cudaGetSymbolAddress((void**)&p_qkv, g_qkv);
    cudaGetSymbolAddress((void**)&p_ao,  g_ao);
    cudaGetSymbolAddress((void**)&p_x1,  g_x1);
    cudaGetSymbolAddress((void**)&p_w,   g_w);
    cudaGetSymbolAddress((void**)&p_ll,  g_ll);
    cudaGetSymbolAddress((void**)&p_cl,  g_cl);
    cudaGetSymbolAddress((void**)&p_qwh, g_qwh);
    cudaGetSymbolAddress((void**)&p_qwl, g_qwl);
    cudaGetSymbolAddress((void**)&p_pwh, g_pwh);
    cudaGetSymbolAddress((void**)&p_pwl, g_pwl);
    cudaGetSymbolAddress((void**)&p_skip, g_skip);

    // opt-in dynamic smem (>48KB); idempotent host-side attr, not captured
    static bool attr_done = false;
    if (!attr_done) {
        cudaFuncSetAttribute(gemmtc2_k<1, true>,
                             cudaFuncAttributeMaxDynamicSharedMemorySize, TC2_SMEM);
        cudaFuncSetAttribute(gemmtc2_k<2, false>,
                             cudaFuncAttributeMaxDynamicSharedMemorySize, TC2_SMEM);
        cudaFuncSetAttribute(attn3_kernel,
                             cudaFuncAttributeMaxDynamicSharedMemorySize, AT_SMEM);
        attr_done = true;
    }

    const int MB128 = NTOK / 128;  // 392
    const int MB64  = NTOK / 64;   // 784

    // 0) guard + weight pre-split + LN1 stats
    guard_kernel<<<1, 1024>>>(tm_inc, tm_out, p_skip);
    splitw_kernel<<<(QKVDIM * CDIM + 255) / 256, 256>>>(
        qkv_w, proj_w, p_qwh, p_qwl, p_pwh, p_pwl);
    ln1_stats<<<NTOK / 8, 256>>>(x, p_mu, p_rs);

    // 2) QKV GEMM (tensor cores, 3xTF32, pre-split weights) with fused LN1
    gemmtc2_k<1, true><<<dim3(MB64, QKVDIM / 96), 256, TC2_SMEM>>>(
        x, p_qwh, p_qwl, qkv_b, nullptr, p_qkv, QKVDIM,
        p_mu, p_rs, n1g, n1b, nullptr, nullptr, p_skip);

    // 3) windowed attention: tensor cores, pre-split K/V fragments
    attn3_kernel<<<dim3(NWIN, 3), 128, AT_SMEM>>>(p_qkv, p_ao);

    // 4) proj + residual (tensor cores); fast path writes final output
    gemmtc2_k<2, false><<<dim3(MB64, 1), 256, TC2_SMEM>>>(
        p_ao, p_pwh, p_pwl, proj_b, x, p_x1, CDIM,
        nullptr, nullptr, nullptr, nullptr, out, gate, p_skip);

    // 5) double layernorm -> g_w   (skipped on fast path)
    ln2_kernel<<<NTOK / 8, 256>>>(p_x1, n2g, n2b, fng, fnb, p_w, p_skip);

    // 6) pin GEMM + sigmoid + log-literals -> g_ll   (skipped on fast path)
    gemm2_k<3, false, false, 1><<<dim3(MB128, (HIDDIM + 127) / 128), 256>>>(
        p_w, pin_w, pin_b, nullptr, nullptr, p_ll,
        NTOK, HIDDIM, CDIM, LITDIM, p_skip);

    // 7) clause GEMM, binary mask, exp epilogue -> g_cl (skipped on fast path)
    gemm2_k<4, false, true, 1><<<dim3(MB128, 1), 256>>>(
        p_ll, tm_inc, nullptr, nullptr, nullptr, p_cl,
        NTOK, NCLAUSE, LITDIM, NCLAUSE, p_skip);

    // 8) final GEMM: full path only (fast path already wrote out in step 4)
    gemm2_k<5, true, false, 1><<<dim3(MB128, 1), 256>>>(
        p_cl, tm_out, nullptr, p_x1, gate, out,
        NTOK, CDIM, NCLAUSE, CDIM, p_skip);

    (void)in_sizes; (void)n_in; (void)out_size;
}

// round 14
// speedup vs baseline: 1.2575x; 1.2575x over previous
#include <cuda_runtime.h>
#include <math.h>
#include <limits.h>

// Problem constants
#define NTOK 50176            // 16 * 56 * 56
#define CDIM 96
#define QKVDIM 288
#define HIDDIM 384
#define LITDIM 768
#define NCLAUSE 128
#define NWIN 1024             // 16 * 8 * 8
#define IMGHW 56
#define LNEPS 1e-5f

// ---------------- scratch (static device arrays; no allocation) -------------
__device__ float g_mu [(size_t)NTOK];
__device__ float g_rs [(size_t)NTOK];
__device__ float g_qkv[(size_t)NTOK * QKVDIM];
__device__ float g_ao [(size_t)NTOK * CDIM];
__device__ float g_x1 [(size_t)NTOK * CDIM];
__device__ float g_w  [(size_t)NTOK * CDIM];
__device__ float g_ll [(size_t)NTOK * LITDIM];
__device__ float g_cl [(size_t)NTOK * NCLAUSE];
__device__ int   g_skip;     // 1 => TM-FFN branch provably ~0, take fast path

// ---------------- helpers ---------------------------------------------------
__device__ __forceinline__ float warp_sum(float v) {
#pragma unroll
    for (int o = 16; o > 0; o >>= 1) v += __shfl_xor_sync(0xffffffffu, v, o);
    return v;
}

__device__ __forceinline__ unsigned f2tf32(float x) {
    unsigned r;
    asm("cvt.rna.tf32.f32 %0, %1;" : "=r"(r) : "f"(x));
    return r;
}

// d += A(16x8) * B(8x8), tf32 operands, f32 accum. Standard m16n8k8 fragments.
__device__ __forceinline__ void mma_tf32(float* d, const unsigned* a,
                                         const unsigned* b) {
    asm("mma.sync.aligned.m16n8k8.row.col.f32.tf32.tf32.f32 "
        "{%0,%1,%2,%3}, {%4,%5,%6,%7}, {%8,%9}, {%0,%1,%2,%3};"
        : "+f"(d[0]), "+f"(d[1]), "+f"(d[2]), "+f"(d[3])
        : "r"(a[0]), "r"(a[1]), "r"(a[2]), "r"(a[3]), "r"(b[0]), "r"(b[1]));
}

#define SPLIT2(hi, lo, x) { hi = f2tf32(x); lo = f2tf32((x) - __uint_as_float(hi)); }

// ---------------- guard: is the clause branch provably negligible? ----------
// Any literal pair (j, j+384) with BOTH mask bits set contributes
// log(max(y,eps)) + log(max(1-y,eps)) <= log(1/4) to the clause exponent S,
// so |logits| <= NCLAUSE * max|tm_out| * exp(-1.386 * min_c n_both(c)).
// Bound < 1e-25 => replacing logits by 0 perturbs output < 1e-25: fast path.
__global__ __launch_bounds__(1024) void guard_kernel(
    const float* __restrict__ tm_inc, const float* __restrict__ tm_out,
    int* __restrict__ flag)
{
    __shared__ int   cnt[1024];
    __shared__ int   csum[NCLAUSE];
    __shared__ float mxs[1024];
    int t = threadIdx.x;
    int c = t >> 3, sub = t & 7;      // 8 threads per clause, 48 pairs each
    const float4* rowA = (const float4*)(tm_inc + (size_t)c * LITDIM);
    const float4* rowB = (const float4*)(tm_inc + (size_t)c * LITDIM + HIDDIM);
    int cn = 0;
    int base = sub * 12;              // 12 float4 = 48 floats
#pragma unroll
    for (int q = 0; q < 12; q++) {
        float4 a = rowA[base + q];
        float4 b = rowB[base + q];
        cn += (a.x > 0.0f && b.x > 0.0f) ? 1 : 0;
        cn += (a.y > 0.0f && b.y > 0.0f) ? 1 : 0;
        cn += (a.z > 0.0f && b.z > 0.0f) ? 1 : 0;
        cn += (a.w > 0.0f && b.w > 0.0f) ? 1 : 0;
    }
    cnt[t] = cn;
    float m = 0.0f;
    const float4* to4 = (const float4*)tm_out;   // 12288 floats = 3072 float4
#pragma unroll
    for (int q = 0; q < 3; q++) {
        float4 v = to4[t + q * 1024];
        m = fmaxf(m, fmaxf(fmaxf(fabsf(v.x), fabsf(v.y)),
                           fmaxf(fabsf(v.z), fabsf(v.w))));
    }
    mxs[t] = m;
    __syncthreads();
    if (t < NCLAUSE) {
        int s = 0;
#pragma unroll
        for (int i = 0; i < 8; i++) s += cnt[t * 8 + i];
        csum[t] = s;
    }
    __syncthreads();
    if (t == 0) {
        int mn = INT_MAX;
        for (int i = 0; i < NCLAUSE; i++) mn = (csum[i] < mn) ? csum[i] : mn;
        float M = 0.0f;
        for (int i = 0; i < 1024; i++) M = fmaxf(M, mxs[i]);
        float logbound = logf((float)NCLAUSE * M + 1e-30f) - 1.3862944f * (float)mn;
        flag[0] = (logbound < -57.6f) ? 1 : 0;   // e^-57.6 ~ 1e-25
    }
}

// ---------------- LN1 stats only (mean + rstd per token) ---------------------
__global__ __launch_bounds__(256) void ln1_stats(
    const float* __restrict__ x, float* __restrict__ mu, float* __restrict__ rs)
{
    int warp = (blockIdx.x * blockDim.x + threadIdx.x) >> 5;
    int lane = threadIdx.x & 31;
    if (warp >= NTOK) return;
    size_t base = (size_t)warp * CDIM;
    float v0 = x[base + lane];
    float v1 = x[base + lane + 32];
    float v2 = x[base + lane + 64];
    float mean = warp_sum(v0 + v1 + v2) * (1.0f / CDIM);
    float d0 = v0 - mean, d1 = v1 - mean, d2 = v2 - mean;
    float var = warp_sum(d0 * d0 + d1 * d1 + d2 * d2) * (1.0f / CDIM);
    if (lane == 0) {
        mu[warp] = mean;
        rs[warp] = rsqrtf(var + LNEPS);
    }
}

// double layernorm: w = LN(LN(x1, g2, b2), fg, fb); early-exit on fast path
__global__ __launch_bounds__(256) void ln2_kernel(
    const float* __restrict__ x, const float* __restrict__ g2,
    const float* __restrict__ b2, const float* __restrict__ fg,
    const float* __restrict__ fb, float* __restrict__ y,
    const int* __restrict__ flag)
{
    if (flag[0]) return;
    int warp = (blockIdx.x * blockDim.x + threadIdx.x) >> 5;
    int lane = threadIdx.x & 31;
    if (warp >= NTOK) return;
    size_t base = (size_t)warp * CDIM;
    float v0 = x[base + lane];
    float v1 = x[base + lane + 32];
    float v2 = x[base + lane + 64];
    float mean = warp_sum(v0 + v1 + v2) * (1.0f / CDIM);
    float d0 = v0 - mean, d1 = v1 - mean, d2 = v2 - mean;
    float var = warp_sum(d0 * d0 + d1 * d1 + d2 * d2) * (1.0f / CDIM);
    float rsv = rsqrtf(var + LNEPS);
    float z0 = d0 * rsv * g2[lane]      + b2[lane];
    float z1 = d1 * rsv * g2[lane + 32] + b2[lane + 32];
    float z2 = d2 * rsv * g2[lane + 64] + b2[lane + 64];
    float m2 = warp_sum(z0 + z1 + z2) * (1.0f / CDIM);
    float e0 = z0 - m2, e1 = z1 - m2, e2 = z2 - m2;
    float var2 = warp_sum(e0 * e0 + e1 * e1 + e2 * e2) * (1.0f / CDIM);
    float rs2 = rsqrtf(var2 + LNEPS);
    y[base + lane]      = e0 * rs2 * fg[lane]      + fb[lane];
    y[base + lane + 32] = e1 * rs2 * fg[lane + 32] + fb[lane + 32];
    y[base + lane + 64] = e2 * rs2 * fg[lane + 64] + fb[lane + 64];
}

// ---------------- TF32 tensor-core GEMM (R12 form: BM=128, in-loop split) ----
// C[M x N] = A[M x 96] @ B^T (+bias), B is N x 96 row-major. BM=128, BN=96.
// One smem load (K=96 entire), 8 warps, warp tile 32x48, mma m16n8k8.
// 3xTF32 split: a = ah + al, b = bh + bl; d += ah*bh + al*bh + ah*bl.
// LNA: A element = (x - mu[m]) * rs[m] * gamma[k] + beta[k] applied at load.
// MODE 1 (qkv): C = acc + bias[n]
// MODE 2 (proj): full path -> C = ex1 + acc + bias
//                fast path -> Cfast = ex1 + acc + bias + (1-sigmoid(gate))*0.5
#define TC_LDA 100   // row pitch (mod 32 == 4 -> conflict-free frag loads)
#define TC_SMEM ((128 * TC_LDA + 96 * TC_LDA) * 4)

template<int MODE, bool LNA>
__global__ __launch_bounds__(256, 2) void gemmtc_k(
    const float* __restrict__ A, const float* __restrict__ B,
    const float* __restrict__ bias, const float* __restrict__ ex1,
    float* __restrict__ C, int ldc,
    const float* __restrict__ MU, const float* __restrict__ RS,
    const float* __restrict__ LNG, const float* __restrict__ LNB,
    float* __restrict__ Cfast, const float* __restrict__ gatep,
    const int* __restrict__ flag)
{
    extern __shared__ float sm[];
    float* As = sm;                    // [128][TC_LDA]
    float* Bs = sm + 128 * TC_LDA;     // [96][TC_LDA]
    __shared__ float gsm[CDIM], bsm[CDIM], bias_sm[96];

    int tid  = threadIdx.x;
    int warp = tid >> 5;
    int lane = tid & 31;
    int gid  = lane >> 2;      // 0..7
    int tig  = lane & 3;       // 0..3
    int m0 = blockIdx.x * 128;
    int n0 = blockIdx.y * 96;
    int mw = (warp & 3) * 32;  // warp m offset
    int nw = (warp >> 2) * 48; // warp n offset

    if (tid < 96) {
        bias_sm[tid] = bias[n0 + tid];
        if (LNA) { gsm[tid] = LNG[tid]; bsm[tid] = LNB[tid]; }
    }

    // load A tile (128 x 96), LN fused; 2 threads per row, 48 cols each
    {
        int r  = tid >> 1;
        int cb = (tid & 1) * 48;
        const float* ap = A + (size_t)(m0 + r) * CDIM + cb;
        float* as = As + r * TC_LDA + cb;
        if (LNA) {
            __syncthreads();   // gsm/bsm ready
            float muv = MU[m0 + r], rsv = RS[m0 + r];
#pragma unroll
            for (int q = 0; q < 12; q++) {
                float4 v = *(const float4*)(ap + q * 4);
                int k = cb + q * 4;
                v.x = (v.x - muv) * rsv * gsm[k]     + bsm[k];
                v.y = (v.y - muv) * rsv * gsm[k + 1] + bsm[k + 1];
                v.z = (v.z - muv) * rsv * gsm[k + 2] + bsm[k + 2];
                v.w = (v.w - muv) * rsv * gsm[k + 3] + bsm[k + 3];
                *(float4*)(as + q * 4) = v;
            }
        } else {
#pragma unroll
            for (int q = 0; q < 12; q++)
                *(float4*)(as + q * 4) = *(const float4*)(ap + q * 4);
        }
    }
    // load B tile (96 x 96): threads 0..191, 2 per row
    if (tid < 192) {
        int r  = tid >> 1;
        int cb = (tid & 1) * 48;
        const float* bp = B + (size_t)(n0 + r) * CDIM + cb;
        float* bs = Bs + r * TC_LDA + cb;
#pragma unroll
        for (int q = 0; q < 12; q++)
            *(float4*)(bs + q * 4) = *(const float4*)(bp + q * 4);
    }
    __syncthreads();

    float acc[2][6][4];
#pragma unroll
    for (int mt = 0; mt < 2; mt++)
#pragma unroll
        for (int nt = 0; nt < 6; nt++)
#pragma unroll
            for (int i = 0; i < 4; i++) acc[mt][nt][i] = 0.0f;

#pragma unroll 2
    for (int kk = 0; kk < 96; kk += 8) {
        unsigned bh[6][2], bl[6][2];
#pragma unroll
        for (int nt = 0; nt < 6; nt++) {
            int rb = (nw + nt * 8 + gid) * TC_LDA + kk + tig;
            float b0f = Bs[rb];
            float b1f = Bs[rb + 4];
            SPLIT2(bh[nt][0], bl[nt][0], b0f);
            SPLIT2(bh[nt][1], bl[nt][1], b1f);
        }
        unsigned ah[2][4], al[2][4];
#pragma unroll
        for (int mt = 0; mt < 2; mt++) {
            int rb = (mw + mt * 16 + gid) * TC_LDA + kk + tig;
            float a0 = As[rb];
            float a1 = As[rb + 8 * TC_LDA];
            float a2 = As[rb + 4];
            float a3 = As[rb + 8 * TC_LDA + 4];
            SPLIT2(ah[mt][0], al[mt][0], a0);
            SPLIT2(ah[mt][1], al[mt][1], a1);
            SPLIT2(ah[mt][2], al[mt][2], a2);
            SPLIT2(ah[mt][3], al[mt][3], a3);
        }
#pragma unroll
        for (int mt = 0; mt < 2; mt++)
#pragma unroll
            for (int nt = 0; nt < 6; nt++) {
                mma_tf32(acc[mt][nt], ah[mt], bh[nt]);
                mma_tf32(acc[mt][nt], al[mt], bh[nt]);
                mma_tf32(acc[mt][nt], ah[mt], bl[nt]);
            }
    }

    // epilogue
    float add = 0.0f;
    float* dst = C;
    if (MODE == 2) {
        if (flag[0]) {
            float gte = 1.0f / (1.0f + expf(-gatep[0]));
            add = (1.0f - gte) * 0.5f;
            dst = Cfast;
        }
    }
#pragma unroll
    for (int mt = 0; mt < 2; mt++) {
#pragma unroll
        for (int nt = 0; nt < 6; nt++) {
            int m1 = m0 + mw + mt * 16 + gid;
            int nc = nw + nt * 8 + tig * 2;      // col within 96-slice
            int n1 = n0 + nc;
            float b0 = bias_sm[nc], b1 = bias_sm[nc + 1];
            float* d = acc[mt][nt];
            if (MODE == 1) {
                float2 v0 = {d[0] + b0, d[1] + b1};
                float2 v1 = {d[2] + b0, d[3] + b1};
                *(float2*)&C[(size_t)m1 * ldc + n1] = v0;
                *(float2*)&C[(size_t)(m1 + 8) * ldc + n1] = v1;
            } else {
                float2 e0 = *(const float2*)&ex1[(size_t)m1 * CDIM + n1];
                float2 e1 = *(const float2*)&ex1[(size_t)(m1 + 8) * CDIM + n1];
                float2 v0 = {e0.x + d[0] + b0 + add, e0.y + d[1] + b1 + add};
                float2 v1 = {e1.x + d[2] + b0 + add, e1.y + d[3] + b1 + add};
                *(float2*)&dst[(size_t)m1 * ldc + n1] = v0;
                *(float2*)&dst[(size_t)(m1 + 8) * ldc + n1] = v1;
            }
        }
    }
}

// ---------------- fp32 tiled GEMM, 128x128x16 (modes 3,4,5; full path only) --
// SKIP=1: early-exit whole kernel when flag set.
template<int MODE, bool BTRANS, bool BMASK, int SKIP>
__global__ __launch_bounds__(256, 2) void gemm2_k(
    const float* __restrict__ A, const float* __restrict__ B,
    const float* __restrict__ bias, const float* __restrict__ ex1,
    const float* __restrict__ ex2, float* __restrict__ C,
    int M, int N, int K, int ldc, const int* __restrict__ flag)
{
    const int BM = 128, BN = 128, BK = 16;

    int tid = threadIdx.x;
    int m0 = blockIdx.x * BM;
    int n0 = blockIdx.y * BN;
    int tx = tid & 15;
    int ty = tid >> 4;

    if (SKIP == 1) {
        if (flag[0]) return;
    }

    __shared__ __align__(16) float As[2][BK][BM + 4];
    __shared__ __align__(16) float Bs[2][BK][BN + 4];

    int lr = tid >> 1;
    int lk = (tid & 1) * 8;
    int bk = tid >> 4;
    int bn = (tid & 15) * 8;

    float acc[8][8];
#pragma unroll
    for (int i = 0; i < 8; i++)
#pragma unroll
        for (int j = 0; j < 8; j++) acc[i][j] = 0.0f;

    float ldA[8], ldB[8];
    int KT = K / BK;

#define GEMM_LOAD(kt)                                                        \
    {                                                                        \
        const float* ap = A + (size_t)(m0 + lr) * K + (kt) * BK + lk;        \
        *(float4*)&ldA[0] = *(const float4*)ap;                              \
        *(float4*)&ldA[4] = *(const float4*)(ap + 4);                        \
        if (!BTRANS) {                                                       \
            int n = n0 + lr;                                                 \
            if (n < N) {                                                     \
                const float* bp = B + (size_t)n * K + (kt) * BK + lk;        \
                *(float4*)&ldB[0] = *(const float4*)bp;                      \
                *(float4*)&ldB[4] = *(const float4*)(bp + 4);                \
            } else {                                                         \
                _Pragma("unroll")                                            \
                for (int j = 0; j < 8; j++) ldB[j] = 0.0f;                   \
            }                                                                \
            if (BMASK) {                                                     \
                _Pragma("unroll")                                            \
                for (int j = 0; j < 8; j++)                                  \
                    ldB[j] = (ldB[j] > 0.0f) ? 1.0f : 0.0f;                  \
            }                                                                \
        } else {                                                             \
            _Pragma("unroll")                                                \
            for (int j = 0; j < 8; j++) {                                    \
                int n = n0 + bn + j;                                         \
                ldB[j] = (n < N)                                             \
                    ? B[(size_t)((kt) * BK + bk) * N + n] : 0.0f;            \
            }                                                                \
        }                                                                    \
    }

#define GEMM_STS(bsel)                                                       \
    {                                                                        \
        _Pragma("unroll")                                                    \
        for (int j = 0; j < 8; j++) As[bsel][lk + j][lr] = ldA[j];           \
        if (!BTRANS) {                                                       \
            _Pragma("unroll")                                                \
            for (int j = 0; j < 8; j++) Bs[bsel][lk + j][lr] = ldB[j];       \
        } else {                                                             \
            _Pragma("unroll")                                                \
            for (int j = 0; j < 8; j++) Bs[bsel][bk][bn + j] = ldB[j];       \
        }                                                                    \
    }

    GEMM_LOAD(0);
    GEMM_STS(0);
    __syncthreads();

    int buf = 0;
    for (int kt = 0; kt < KT; kt++) {
        if (kt + 1 < KT) GEMM_LOAD(kt + 1);
#pragma unroll
        for (int k = 0; k < BK; k++) {
            float4 a0 = *(const float4*)&As[buf][k][ty * 4];
            float4 a1 = *(const float4*)&As[buf][k][ty * 4 + 64];
            float4 b0 = *(const float4*)&Bs[buf][k][tx * 4];
            float4 b1 = *(const float4*)&Bs[buf][k][tx * 4 + 64];
            float a[8] = {a0.x, a0.y, a0.z, a0.w, a1.x, a1.y, a1.z, a1.w};
            float b[8] = {b0.x, b0.y, b0.z, b0.w, b1.x, b1.y, b1.z, b1.w};
#pragma unroll
            for (int i = 0; i < 8; i++)
#pragma unroll
                for (int j = 0; j < 8; j++) acc[i][j] += a[i] * b[j];
        }
        if (kt + 1 < KT) {
            GEMM_STS(buf ^ 1);
            __syncthreads();
        }
        buf ^= 1;
    }

    float gte = 0.0f;
    if (MODE == 5) gte = 1.0f / (1.0f + expf(-ex2[0]));
#pragma unroll
    for (int i = 0; i < 8; i++) {
        int m = m0 + ty * 4 + (i < 4 ? i : 60 + i);
#pragma unroll
        for (int j = 0; j < 8; j++) {
            int n = n0 + tx * 4 + (j < 4 ? j : 60 + j);
            if (n >= N) continue;
            float v = acc[i][j];
            if (MODE == 3) {
                float y = 1.0f / (1.0f + expf(-(v + bias[n])));
                C[(size_t)m * LITDIM + n]          = logf(fmaxf(y, 1e-6f));
                C[(size_t)m * LITDIM + HIDDIM + n] = logf(fmaxf(1.0f - y, 1e-6f));
            } else if (MODE == 4) {
                C[(size_t)m * ldc + n] = expf(v);
            } else if (MODE == 5) {
                float s = 1.0f / (1.0f + expf(-v));
                C[(size_t)m * ldc + n] = ex1[(size_t)m * CDIM + n] + gte * v + (1.0f - gte) * s;
            }
        }
    }
#undef GEMM_LOAD
#undef GEMM_STS
}

// ---------------- windowed attention, tensor cores + pre-split K/V -----------
// grid (NWIN, 3), block 128 (4 warps). K and V fragments pre-split to tf32
// hi/lo in smem at load (1x per element instead of 1x per warp = 4x fewer cvt).
#define AT_SMEM ((64*36 + 2*56*36 + 2*32*60 + 64*60) * 4)

__global__ __launch_bounds__(128) void attn3_kernel(
    const float* __restrict__ qkv, float* __restrict__ ao)
{
    extern __shared__ float smf[];
    float* qs  = smf;                  // 64*36 (fp32 Q, rows 49..63 zero)
    float* ksh = qs  + 64 * 36;        // 56*36 (tf32-hi K, rows 49..55 zero)
    float* ksl = ksh + 56 * 36;
    float* vth = ksl + 56 * 36;        // 32*60 (tf32-hi V^T, cols 49..55 zero)
    float* vtl = vth + 32 * 60;
    float* ps  = vtl + 32 * 60;        // 64*60 (scores; cols 49..59 zeroed)
    __shared__ int ltab[49];
    __shared__ int otab[49];

    int w  = blockIdx.x;
    int h  = blockIdx.y;
    int b  = w >> 6;
    int wh = (w >> 3) & 7;
    int ww = w & 7;
    int tid  = threadIdx.x;
    int warp = tid >> 5;
    int lane = tid & 31;
    int gid  = lane >> 2;     // 0..7
    int tig  = lane & 3;      // 0..3

    if (tid < 49) {
        int th = tid / 7, tw = tid % 7;
        int r = (wh * 7 + th + 3) % IMGHW;
        int c = (ww * 7 + tw + 3) % IMGHW;
        ltab[tid] = b * (IMGHW * IMGHW) + r * IMGHW + c;
        int ro = wh * 7 + (th + 3) % 7;          // intra-window inverse roll
        int co = ww * 7 + (tw + 3) % 7;
        otab[tid] = b * (IMGHW * IMGHW) + ro * IMGHW + co;
    }
    // zero pads
    for (int i = tid; i < 15 * 36; i += 128) qs[(49 + i / 36) * 36 + i % 36] = 0.0f;
    for (int i = tid; i < 7 * 36; i += 128) {
        ksh[(49 + i / 36) * 36 + i % 36] = 0.0f;
        ksl[(49 + i / 36) * 36 + i % 36] = 0.0f;
    }
    for (int i = tid; i < 32 * 11; i += 128) {
        vth[(i / 11) * 60 + 49 + i % 11] = 0.0f;
        vtl[(i / 11) * 60 + 49 + i % 11] = 0.0f;
    }
    for (int i = tid; i < 64 * 11; i += 128)    // ps pad cols 49..59 all rows
        ps[(i / 11) * 60 + 49 + i % 11] = 0.0f;
    __syncthreads();

    // load q (fp32) and pre-split k, v(transposed) into hi/lo
    for (int i = tid; i < 49 * 8; i += 128) {
        int t = i >> 3, dq = (i & 7) * 4;
        const float* base = qkv + (size_t)ltab[t] * QKVDIM + h * 32 + dq;
        *(float4*)&qs[t * 36 + dq] = *(const float4*)base;
        float4 kv = *(const float4*)(base + 96);
        float4 vv = *(const float4*)(base + 192);
        unsigned hh, ll;
        SPLIT2(hh, ll, kv.x); ksh[t*36+dq]   = __uint_as_float(hh); ksl[t*36+dq]   = __uint_as_float(ll);
        SPLIT2(hh, ll, kv.y); ksh[t*36+dq+1] = __uint_as_float(hh); ksl[t*36+dq+1] = __uint_as_float(ll);
        SPLIT2(hh, ll, kv.z); ksh[t*36+dq+2] = __uint_as_float(hh); ksl[t*36+dq+2] = __uint_as_float(ll);
        SPLIT2(hh, ll, kv.w); ksh[t*36+dq+3] = __uint_as_float(hh); ksl[t*36+dq+3] = __uint_as_float(ll);
        SPLIT2(hh, ll, vv.x); vth[(dq)*60+t]   = __uint_as_float(hh); vtl[(dq)*60+t]   = __uint_as_float(ll);
        SPLIT2(hh, ll, vv.y); vth[(dq+1)*60+t] = __uint_as_float(hh); vtl[(dq+1)*60+t] = __uint_as_float(ll);
        SPLIT2(hh, ll, vv.z); vth[(dq+2)*60+t] = __uint_as_float(hh); vtl[(dq+2)*60+t] = __uint_as_float(ll);
        SPLIT2(hh, ll, vv.w); vth[(dq+3)*60+t] = __uint_as_float(hh); vtl[(dq+3)*60+t] = __uint_as_float(ll);
    }
    __syncthreads();

    const float scale = 0.17677669529663687f;  // 1/sqrt(32)

    // ---- scores: warp = m-tile (16 rows); 7 n-tiles x 4 k-tiles x 3 mma ----
    {
        int mrow = warp * 16 + gid;
        unsigned ah[4][4], al[4][4];
#pragma unroll
        for (int kt = 0; kt < 4; kt++) {
            int kc = kt * 8 + tig;
            float a0 = qs[mrow * 36 + kc];
            float a1 = qs[(mrow + 8) * 36 + kc];
            float a2 = qs[mrow * 36 + kc + 4];
            float a3 = qs[(mrow + 8) * 36 + kc + 4];
            SPLIT2(ah[kt][0], al[kt][0], a0);
            SPLIT2(ah[kt][1], al[kt][1], a1);
            SPLIT2(ah[kt][2], al[kt][2], a2);
            SPLIT2(ah[kt][3], al[kt][3], a3);
        }
#pragma unroll
        for (int nt = 0; nt < 7; nt++) {
            unsigned bh[4][2], bl[4][2];
#pragma unroll
            for (int kt = 0; kt < 4; kt++) {
                int rb = (nt * 8 + gid) * 36 + kt * 8 + tig;
                bh[kt][0] = __float_as_uint(ksh[rb]);
                bh[kt][1] = __float_as_uint(ksh[rb + 4]);
                bl[kt][0] = __float_as_uint(ksl[rb]);
                bl[kt][1] = __float_as_uint(ksl[rb + 4]);
            }
            float acc[4] = {0.0f, 0.0f, 0.0f, 0.0f};
#pragma unroll
            for (int kt = 0; kt < 4; kt++) {
                mma_tf32(acc, ah[kt], bh[kt]);
                mma_tf32(acc, al[kt], bh[kt]);
                mma_tf32(acc, ah[kt], bl[kt]);
            }
            int c = nt * 8 + tig * 2;
            if (c < 49) {
                ps[mrow * 60 + c]       = acc[0] * scale;
                ps[(mrow + 8) * 60 + c] = acc[2] * scale;
            }
            if (c + 1 < 49) {
                ps[mrow * 60 + c + 1]       = acc[1] * scale;
                ps[(mrow + 8) * 60 + c + 1] = acc[3] * scale;
            }
        }
    }
    __syncthreads();

    // softmax: 2 threads per row (rows 0..48); pad cols already zero
    if (tid < 98) {
        int row = tid >> 1, half = tid & 1;
        int c0 = half ? 25 : 0;
        int c1 = half ? 49 : 25;
        unsigned mask = (tid < 96) ? 0xffffffffu : 0x3u;
        float mx = -1e30f;
        for (int j = c0; j < c1; j++) mx = fmaxf(mx, ps[row * 60 + j]);
        mx = fmaxf(mx, __shfl_xor_sync(mask, mx, 1));
        float sum = 0.0f;
        for (int j = c0; j < c1; j++) {
            float e = expf(ps[row * 60 + j] - mx);
            ps[row * 60 + j] = e;
            sum += e;
        }
        sum += __shfl_xor_sync(mask, sum, 1);
        float inv = 1.0f / sum;
        for (int j = c0; j < c1; j++) ps[row * 60 + j] *= inv;
    }
    __syncthreads();

    // ---- AV: O(64x32) = P @ V; warp = m-tile; 4 n-tiles x 7 k-tiles x 3 ----
    {
        int mrow = warp * 16 + gid;
        unsigned ah[7][4], al[7][4];
#pragma unroll
        for (int kt = 0; kt < 7; kt++) {
            int kc = kt * 8 + tig;
            float a0 = ps[mrow * 60 + kc];
            float a1 = ps[(mrow + 8) * 60 + kc];
            float a2 = ps[mrow * 60 + kc + 4];
            float a3 = ps[(mrow + 8) * 60 + kc + 4];
            SPLIT2(ah[kt][0], al[kt][0], a0);
            SPLIT2(ah[kt][1], al[kt][1], a1);
            SPLIT2(ah[kt][2], al[kt][2], a2);
            SPLIT2(ah[kt][3], al[kt][3], a3);
        }
#pragma unroll
        for (int nt = 0; nt < 4; nt++) {
            unsigned bh[7][2], bl[7][2];
#pragma unroll
            for (int kt = 0; kt < 7; kt++) {
                int rb = (nt * 8 + gid) * 60 + kt * 8 + tig;
                bh[kt][0] = __float_as_uint(vth[rb]);
                bh[kt][1] = __float_as_uint(vth[rb + 4]);
                bl[kt][0] = __float_as_uint(vtl[rb]);
                bl[kt][1] = __float_as_uint(vtl[rb + 4]);
            }
            float acc[4] = {0.0f, 0.0f, 0.0f, 0.0f};
#pragma unroll
            for (int kt = 0; kt < 7; kt++) {
                mma_tf32(acc, ah[kt], bh[kt]);
                mma_tf32(acc, al[kt], bh[kt]);
                mma_tf32(acc, ah[kt], bl[kt]);
            }
            int d = nt * 8 + tig * 2;
            int t0 = mrow, t1 = mrow + 8;
            if (t0 < 49) {
                float2 o = {acc[0], acc[1]};
                *(float2*)&ao[(size_t)otab[t0] * CDIM + h * 32 + d] = o;
            }
            if (t1 < 49) {
                float2 o = {acc[2], acc[3]};
                *(float2*)&ao[(size_t)otab[t1] * CDIM + h * 32 + d] = o;
            }
        }
    }
}

// ---------------- host launcher ----------------------------------------------
extern "C" void kernel_launch(void* const* d_in, const int* in_sizes, int n_in,
                              void* d_out, int out_size)
{
    const float* x       = (const float*)d_in[0];
    const float* n1g     = (const float*)d_in[1];
    const float* n1b     = (const float*)d_in[2];
    const float* qkv_w   = (const float*)d_in[3];
    const float* qkv_b   = (const float*)d_in[4];
    const float* proj_w  = (const float*)d_in[5];
    const float* proj_b  = (const float*)d_in[6];
    const float* n2g     = (const float*)d_in[7];
    const float* n2b     = (const float*)d_in[8];
    const float* fng     = (const float*)d_in[9];
    const float* fnb     = (const float*)d_in[10];
    const float* pin_w   = (const float*)d_in[11];
    const float* pin_b   = (const float*)d_in[12];
    const float* tm_inc  = (const float*)d_in[13];
    const float* tm_out  = (const float*)d_in[14];
    const float* gate    = (const float*)d_in[15];
    float* out           = (float*)d_out;

    float *p_mu, *p_rs, *p_qkv, *p_ao, *p_x1, *p_w, *p_ll, *p_cl;
    int* p_skip;
    cudaGetSymbolAddress((void**)&p_mu,  g_mu);
    cudaGetSymbolAddress((void**)&p_rs,  g_rs);
    cudaGetSymbolAddress((void**)&p_qkv, g_qkv);
    cudaGetSymbolAddress((void**)&p_ao,  g_ao);
    cudaGetSymbolAddress((void**)&p_x1,  g_x1);
    cudaGetSymbolAddress((void**)&p_w,   g_w);
    cudaGetSymbolAddress((void**)&p_ll,  g_ll);
    cudaGetSymbolAddress((void**)&p_cl,  g_cl);
    cudaGetSymbolAddress((void**)&p_skip, g_skip);

    // opt-in dynamic smem (>48KB); idempotent host-side attr, not captured
    static bool attr_done = false;
    if (!attr_done) {
        cudaFuncSetAttribute(gemmtc_k<1, true>,
                             cudaFuncAttributeMaxDynamicSharedMemorySize, TC_SMEM);
        cudaFuncSetAttribute(gemmtc_k<2, false>,
                             cudaFuncAttributeMaxDynamicSharedMemorySize, TC_SMEM);
        cudaFuncSetAttribute(attn3_kernel,
                             cudaFuncAttributeMaxDynamicSharedMemorySize, AT_SMEM);
        attr_done = true;
    }

    const int MB = NTOK / 128;  // 392

    // 0) guard + LN1 stats
    guard_kernel<<<1, 1024>>>(tm_inc, tm_out, p_skip);
    ln1_stats<<<NTOK / 8, 256>>>(x, p_mu, p_rs);

    // 2) QKV GEMM (tensor cores, 3xTF32, BM=128) with fused LN1
    gemmtc_k<1, true><<<dim3(MB, QKVDIM / 96), 256, TC_SMEM>>>(
        x, qkv_w, qkv_b, nullptr, p_qkv, QKVDIM,
        p_mu, p_rs, n1g, n1b, nullptr, nullptr, p_skip);

    // 3) windowed attention: tensor cores, pre-split K/V fragments
    attn3_kernel<<<dim3(NWIN, 3), 128, AT_SMEM>>>(p_qkv, p_ao);

    // 4) proj + residual (tensor cores); fast path writes final output
    gemmtc_k<2, false><<<dim3(MB, 1), 256, TC_SMEM>>>(
        p_ao, proj_w, proj_b, x, p_x1, CDIM,
        nullptr, nullptr, nullptr, nullptr, out, gate, p_skip);

    // 5) double layernorm -> g_w   (skipped on fast path)
    ln2_kernel<<<NTOK / 8, 256>>>(p_x1, n2g, n2b, fng, fnb, p_w, p_skip);

    // 6) pin GEMM + sigmoid + log-literals -> g_ll   (skipped on fast path)
    gemm2_k<3, false, false, 1><<<dim3(MB, (HIDDIM + 127) / 128), 256>>>(
        p_w, pin_w, pin_b, nullptr, nullptr, p_ll,
        NTOK, HIDDIM, CDIM, LITDIM, p_skip);

    // 7) clause GEMM, binary mask, exp epilogue -> g_cl (skipped on fast path)
    gemm2_k<4, false, true, 1><<<dim3(MB, 1), 256>>>(
        p_ll, tm_inc, nullptr, nullptr, nullptr, p_cl,
        NTOK, NCLAUSE, LITDIM, NCLAUSE, p_skip);

    // 8) final GEMM: full path only (fast path already wrote out in step 4)
    gemm2_k<5, true, false, 1><<<dim3(MB, 1), 256>>>(
        p_cl, tm_out, nullptr, p_x1, gate, out,
        NTOK, CDIM, NCLAUSE, CDIM, p_skip);

    (void)in_sizes; (void)n_in; (void)out_size;
}

// round 15
// speedup vs baseline: 1.3335x; 1.0604x over previous
#include <cuda_runtime.h>
#include <math.h>
#include <limits.h>

// Problem constants
#define NTOK 50176            // 16 * 56 * 56
#define CDIM 96
#define QKVDIM 288
#define HIDDIM 384
#define LITDIM 768
#define NCLAUSE 128
#define NWIN 1024             // 16 * 8 * 8
#define IMGHW 56
#define LNEPS 1e-5f

// ---------------- scratch (static device arrays; no allocation) -------------
__device__ float g_qkv[(size_t)NTOK * QKVDIM];
__device__ float g_ao [(size_t)NTOK * CDIM];
__device__ float g_x1 [(size_t)NTOK * CDIM];
__device__ float g_w  [(size_t)NTOK * CDIM];
__device__ float g_ll [(size_t)NTOK * LITDIM];
__device__ float g_cl [(size_t)NTOK * NCLAUSE];
__device__ int   g_skip;     // 1 => TM-FFN branch provably ~0, take fast path

// ---------------- helpers ---------------------------------------------------
__device__ __forceinline__ float warp_sum(float v) {
#pragma unroll
    for (int o = 16; o > 0; o >>= 1) v += __shfl_xor_sync(0xffffffffu, v, o);
    return v;
}

__device__ __forceinline__ unsigned f2tf32(float x) {
    unsigned r;
    asm("cvt.rna.tf32.f32 %0, %1;" : "=r"(r) : "f"(x));
    return r;
}

// d += A(16x8) * B(8x8), tf32 operands, f32 accum. Standard m16n8k8 fragments.
__device__ __forceinline__ void mma_tf32(float* d, const unsigned* a,
                                         const unsigned* b) {
    asm("mma.sync.aligned.m16n8k8.row.col.f32.tf32.tf32.f32 "
        "{%0,%1,%2,%3}, {%4,%5,%6,%7}, {%8,%9}, {%0,%1,%2,%3};"
        : "+f"(d[0]), "+f"(d[1]), "+f"(d[2]), "+f"(d[3])
        : "r"(a[0]), "r"(a[1]), "r"(a[2]), "r"(a[3]), "r"(b[0]), "r"(b[1]));
}

#define SPLIT2(hi, lo, x) { hi = f2tf32(x); lo = f2tf32((x) - __uint_as_float(hi)); }

// ---------------- guard: is the clause branch provably negligible? ----------
// Any literal pair (j, j+384) with BOTH mask bits set contributes
// log(max(y,eps)) + log(max(1-y,eps)) <= log(1/4) to the clause exponent S,
// so |logits| <= NCLAUSE * max|tm_out| * exp(-1.386 * min_c n_both(c)).
// Bound < 1e-25 => replacing logits by 0 perturbs output < 1e-25: fast path.
__global__ __launch_bounds__(1024) void guard_kernel(
    const float* __restrict__ tm_inc, const float* __restrict__ tm_out,
    int* __restrict__ flag)
{
    __shared__ int   cnt[1024];
    __shared__ int   csum[NCLAUSE];
    __shared__ float mxs[1024];
    int t = threadIdx.x;
    int c = t >> 3, sub = t & 7;      // 8 threads per clause, 48 pairs each
    const float4* rowA = (const float4*)(tm_inc + (size_t)c * LITDIM);
    const float4* rowB = (const float4*)(tm_inc + (size_t)c * LITDIM + HIDDIM);
    int cn = 0;
    int base = sub * 12;              // 12 float4 = 48 floats
#pragma unroll
    for (int q = 0; q < 12; q++) {
        float4 a = rowA[base + q];
        float4 b = rowB[base + q];
        cn += (a.x > 0.0f && b.x > 0.0f) ? 1 : 0;
        cn += (a.y > 0.0f && b.y > 0.0f) ? 1 : 0;
        cn += (a.z > 0.0f && b.z > 0.0f) ? 1 : 0;
        cn += (a.w > 0.0f && b.w > 0.0f) ? 1 : 0;
    }
    cnt[t] = cn;
    float m = 0.0f;
    const float4* to4 = (const float4*)tm_out;   // 12288 floats = 3072 float4
#pragma unroll
    for (int q = 0; q < 3; q++) {
        float4 v = to4[t + q * 1024];
        m = fmaxf(m, fmaxf(fmaxf(fabsf(v.x), fabsf(v.y)),
                           fmaxf(fabsf(v.z), fabsf(v.w))));
    }
    mxs[t] = m;
    __syncthreads();
    if (t < NCLAUSE) {
        int s = 0;
#pragma unroll
        for (int i = 0; i < 8; i++) s += cnt[t * 8 + i];
        csum[t] = s;
    }
    __syncthreads();
    if (t == 0) {
        int mn = INT_MAX;
        for (int i = 0; i < NCLAUSE; i++) mn = (csum[i] < mn) ? csum[i] : mn;
        float M = 0.0f;
        for (int i = 0; i < 1024; i++) M = fmaxf(M, mxs[i]);
        float logbound = logf((float)NCLAUSE * M + 1e-30f) - 1.3862944f * (float)mn;
        flag[0] = (logbound < -57.6f) ? 1 : 0;   // e^-57.6 ~ 1e-25
    }
}

// double layernorm: w = LN(LN(x1, g2, b2), fg, fb); early-exit on fast path
__global__ __launch_bounds__(256) void ln2_kernel(
    const float* __restrict__ x, const float* __restrict__ g2,
    const float* __restrict__ b2, const float* __restrict__ fg,
    const float* __restrict__ fb, float* __restrict__ y,
    const int* __restrict__ flag)
{
    if (flag[0]) return;
    int warp = (blockIdx.x * blockDim.x + threadIdx.x) >> 5;
    int lane = threadIdx.x & 31;
    if (warp >= NTOK) return;
    size_t base = (size_t)warp * CDIM;
    float v0 = x[base + lane];
    float v1 = x[base + lane + 32];
    float v2 = x[base + lane + 64];
    float mean = warp_sum(v0 + v1 + v2) * (1.0f / CDIM);
    float d0 = v0 - mean, d1 = v1 - mean, d2 = v2 - mean;
    float var = warp_sum(d0 * d0 + d1 * d1 + d2 * d2) * (1.0f / CDIM);
    float rsv = rsqrtf(var + LNEPS);
    float z0 = d0 * rsv * g2[lane]      + b2[lane];
    float z1 = d1 * rsv * g2[lane + 32] + b2[lane + 32];
    float z2 = d2 * rsv * g2[lane + 64] + b2[lane + 64];
    float m2 = warp_sum(z0 + z1 + z2) * (1.0f / CDIM);
    float e0 = z0 - m2, e1 = z1 - m2, e2 = z2 - m2;
    float var2 = warp_sum(e0 * e0 + e1 * e1 + e2 * e2) * (1.0f / CDIM);
    float rs2 = rsqrtf(var2 + LNEPS);
    y[base + lane]      = e0 * rs2 * fg[lane]      + fb[lane];
    y[base + lane + 32] = e1 * rs2 * fg[lane + 32] + fb[lane + 32];
    y[base + lane + 64] = e2 * rs2 * fg[lane + 64] + fb[lane + 64];
}

// ---------------- TF32 tensor-core GEMM (BM=128; LN1 stats fused in-load) ----
// C[M x N] = A[M x 96] @ B^T (+bias), B is N x 96 row-major. BM=128, BN=96.
// One smem load (K=96 entire), 8 warps, warp tile 32x48, mma m16n8k8.
// 3xTF32 split: a = ah + al, b = bh + bl; d += ah*bh + al*bh + ah*bl.
// LNA: full per-token layernorm computed in the A-load (2 threads/row, shfl
//      pair reduction; var = E[x^2] - mu^2) then applied with gamma/beta.
// MODE 1 (qkv): C = acc + bias[n]
// MODE 2 (proj): full path -> C = ex1 + acc + bias
//                fast path -> Cfast = ex1 + acc + bias + (1-sigmoid(gate))*0.5
#define TC_LDA 100   // row pitch (mod 32 == 4 -> conflict-free frag loads)
#define TC_SMEM ((128 * TC_LDA + 96 * TC_LDA) * 4)

template<int MODE, bool LNA>
__global__ __launch_bounds__(256, 2) void gemmtc_k(
    const float* __restrict__ A, const float* __restrict__ B,
    const float* __restrict__ bias, const float* __restrict__ ex1,
    float* __restrict__ C, int ldc,
    const float* __restrict__ LNG, const float* __restrict__ LNB,
    float* __restrict__ Cfast, const float* __restrict__ gatep,
    const int* __restrict__ flag)
{
    extern __shared__ float sm[];
    float* As = sm;                    // [128][TC_LDA]
    float* Bs = sm + 128 * TC_LDA;     // [96][TC_LDA]
    __shared__ float gsm[CDIM], bsm[CDIM], bias_sm[96];

    int tid  = threadIdx.x;
    int warp = tid >> 5;
    int lane = tid & 31;
    int gid  = lane >> 2;      // 0..7
    int tig  = lane & 3;       // 0..3
    int m0 = blockIdx.x * 128;
    int n0 = blockIdx.y * 96;
    int mw = (warp & 3) * 32;  // warp m offset
    int nw = (warp >> 2) * 48; // warp n offset

    if (tid < 96) {
        bias_sm[tid] = bias[n0 + tid];
        if (LNA) { gsm[tid] = LNG[tid]; bsm[tid] = LNB[tid]; }
    }

    // load A tile (128 x 96); 2 threads per row, 48 cols each.
    // LNA: store raw, reduce stats across the thread pair, normalize in smem.
    {
        int r  = tid >> 1;
        int cb = (tid & 1) * 48;
        const float* ap = A + (size_t)(m0 + r) * CDIM + cb;
        float* as = As + r * TC_LDA + cb;
        if (LNA) {
            float s1 = 0.0f, s2 = 0.0f;
#pragma unroll
            for (int q = 0; q < 12; q++) {
                float4 v = *(const float4*)(ap + q * 4);
                *(float4*)(as + q * 4) = v;
                s1 += v.x + v.y + v.z + v.w;
                s2 += v.x * v.x + v.y * v.y + v.z * v.z + v.w * v.w;
            }
            s1 += __shfl_xor_sync(0xffffffffu, s1, 1);
            s2 += __shfl_xor_sync(0xffffffffu, s2, 1);
            float mean = s1 * (1.0f / CDIM);
            float var  = s2 * (1.0f / CDIM) - mean * mean;
            float rsv  = rsqrtf(var + LNEPS);
            __syncthreads();   // gsm/bsm visible; raw As writes done pairwise anyway
#pragma unroll
            for (int q = 0; q < 12; q++) {
                float4 v = *(const float4*)(as + q * 4);
                int k = cb + q * 4;
                v.x = (v.x - mean) * rsv * gsm[k]     + bsm[k];
                v.y = (v.y - mean) * rsv * gsm[k + 1] + bsm[k + 1];
                v.z = (v.z - mean) * rsv * gsm[k + 2] + bsm[k + 2];
                v.w = (v.w - mean) * rsv * gsm[k + 3] + bsm[k + 3];
                *(float4*)(as + q * 4) = v;
            }
        } else {
#pragma unroll
            for (int q = 0; q < 12; q++)
                *(float4*)(as + q * 4) = *(const float4*)(ap + q * 4);
        }
    }
    // load B tile (96 x 96): threads 0..191, 2 per row
    if (tid < 192) {
        int r  = tid >> 1;
        int cb = (tid & 1) * 48;
        const float* bp = B + (size_t)(n0 + r) * CDIM + cb;
        float* bs = Bs + r * TC_LDA + cb;
#pragma unroll
        for (int q = 0; q < 12; q++)
            *(float4*)(bs + q * 4) = *(const float4*)(bp + q * 4);
    }
    __syncthreads();

    float acc[2][6][4];
#pragma unroll
    for (int mt = 0; mt < 2; mt++)
#pragma unroll
        for (int nt = 0; nt < 6; nt++)
#pragma unroll
            for (int i = 0; i < 4; i++) acc[mt][nt][i] = 0.0f;

#pragma unroll 2
    for (int kk = 0; kk < 96; kk += 8) {
        unsigned bh[6][2], bl[6][2];
#pragma unroll
        for (int nt = 0; nt < 6; nt++) {
            int rb = (nw + nt * 8 + gid) * TC_LDA + kk + tig;
            float b0f = Bs[rb];
            float b1f = Bs[rb + 4];
            SPLIT2(bh[nt][0], bl[nt][0], b0f);
            SPLIT2(bh[nt][1], bl[nt][1], b1f);
        }
        unsigned ah[2][4], al[2][4];
#pragma unroll
        for (int mt = 0; mt < 2; mt++) {
            int rb = (mw + mt * 16 + gid) * TC_LDA + kk + tig;
            float a0 = As[rb];
            float a1 = As[rb + 8 * TC_LDA];
            float a2 = As[rb + 4];
            float a3 = As[rb + 8 * TC_LDA + 4];
            SPLIT2(ah[mt][0], al[mt][0], a0);
            SPLIT2(ah[mt][1], al[mt][1], a1);
            SPLIT2(ah[mt][2], al[mt][2], a2);
            SPLIT2(ah[mt][3], al[mt][3], a3);
        }
#pragma unroll
        for (int mt = 0; mt < 2; mt++)
#pragma unroll
            for (int nt = 0; nt < 6; nt++) {
                mma_tf32(acc[mt][nt], ah[mt], bh[nt]);
                mma_tf32(acc[mt][nt], al[mt], bh[nt]);
                mma_tf32(acc[mt][nt], ah[mt], bl[nt]);
            }
    }

    // epilogue
    float add = 0.0f;
    float* dst = C;
    if (MODE == 2) {
        if (flag[0]) {
            float gte = 1.0f / (1.0f + expf(-gatep[0]));
            add = (1.0f - gte) * 0.5f;
            dst = Cfast;
        }
    }
#pragma unroll
    for (int mt = 0; mt < 2; mt++) {
#pragma unroll
        for (int nt = 0; nt < 6; nt++) {
            int m1 = m0 + mw + mt * 16 + gid;
            int nc = nw + nt * 8 + tig * 2;      // col within 96-slice
            int n1 = n0 + nc;
            float b0 = bias_sm[nc], b1 = bias_sm[nc + 1];
            float* d = acc[mt][nt];
            if (MODE == 1) {
                float2 v0 = {d[0] + b0, d[1] + b1};
                float2 v1 = {d[2] + b0, d[3] + b1};
                *(float2*)&C[(size_t)m1 * ldc + n1] = v0;
                *(float2*)&C[(size_t)(m1 + 8) * ldc + n1] = v1;
            } else {
                float2 e0 = *(const float2*)&ex1[(size_t)m1 * CDIM + n1];
                float2 e1 = *(const float2*)&ex1[(size_t)(m1 + 8) * CDIM + n1];
                float2 v0 = {e0.x + d[0] + b0 + add, e0.y + d[1] + b1 + add};
                float2 v1 = {e1.x + d[2] + b0 + add, e1.y + d[3] + b1 + add};
                *(float2*)&dst[(size_t)m1 * ldc + n1] = v0;
                *(float2*)&dst[(size_t)(m1 + 8) * ldc + n1] = v1;
            }
        }
    }
}

// ---------------- fp32 tiled GEMM, 128x128x16 (modes 3,4,5; full path only) --
// SKIP=1: early-exit whole kernel when flag set.
template<int MODE, bool BTRANS, bool BMASK, int SKIP>
__global__ __launch_bounds__(256, 2) void gemm2_k(
    const float* __restrict__ A, const float* __restrict__ B,
    const float* __restrict__ bias, const float* __restrict__ ex1,
    const float* __restrict__ ex2, float* __restrict__ C,
    int M, int N, int K, int ldc, const int* __restrict__ flag)
{
    const int BM = 128, BN = 128, BK = 16;

    int tid = threadIdx.x;
    int m0 = blockIdx.x * BM;
    int n0 = blockIdx.y * BN;
    int tx = tid & 15;
    int ty = tid >> 4;

    if (SKIP == 1) {
        if (flag[0]) return;
    }

    __shared__ __align__(16) float As[2][BK][BM + 4];
    __shared__ __align__(16) float Bs[2][BK][BN + 4];

    int lr = tid >> 1;
    int lk = (tid & 1) * 8;
    int bk = tid >> 4;
    int bn = (tid & 15) * 8;

    float acc[8][8];
#pragma unroll
    for (int i = 0; i < 8; i++)
#pragma unroll
        for (int j = 0; j < 8; j++) acc[i][j] = 0.0f;

    float ldA[8], ldB[8];
    int KT = K / BK;

#define GEMM_LOAD(kt)                                                        \
    {                                                                        \
        const float* ap = A + (size_t)(m0 + lr) * K + (kt) * BK + lk;        \
        *(float4*)&ldA[0] = *(const float4*)ap;                              \
        *(float4*)&ldA[4] = *(const float4*)(ap + 4);                        \
        if (!BTRANS) {                                                       \
            int n = n0 + lr;                                                 \
            if (n < N) {                                                     \
                const float* bp = B + (size_t)n * K + (kt) * BK + lk;        \
                *(float4*)&ldB[0] = *(const float4*)bp;                      \
                *(float4*)&ldB[4] = *(const float4*)(bp + 4);                \
            } else {                                                         \
                _Pragma("unroll")                                            \
                for (int j = 0; j < 8; j++) ldB[j] = 0.0f;                   \
            }                                                                \
            if (BMASK) {                                                     \
                _Pragma("unroll")                                            \
                for (int j = 0; j < 8; j++)                                  \
                    ldB[j] = (ldB[j] > 0.0f) ? 1.0f : 0.0f;                  \
            }                                                                \
        } else {                                                             \
            _Pragma("unroll")                                                \
            for (int j = 0; j < 8; j++) {                                    \
                int n = n0 + bn + j;                                         \
                ldB[j] = (n < N)                                             \
                    ? B[(size_t)((kt) * BK + bk) * N + n] : 0.0f;            \
            }                                                                \
        }                                                                    \
    }

#define GEMM_STS(bsel)                                                       \
    {                                                                        \
        _Pragma("unroll")                                                    \
        for (int j = 0; j < 8; j++) As[bsel][lk + j][lr] = ldA[j];           \
        if (!BTRANS) {                                                       \
            _Pragma("unroll")                                                \
            for (int j = 0; j < 8; j++) Bs[bsel][lk + j][lr] = ldB[j];       \
        } else {                                                             \
            _Pragma("unroll")                                                \
            for (int j = 0; j < 8; j++) Bs[bsel][bk][bn + j] = ldB[j];       \
        }                                                                    \
    }

    GEMM_LOAD(0);
    GEMM_STS(0);
    __syncthreads();

    int buf = 0;
    for (int kt = 0; kt < KT; kt++) {
        if (kt + 1 < KT) GEMM_LOAD(kt + 1);
#pragma unroll
        for (int k = 0; k < BK; k++) {
            float4 a0 = *(const float4*)&As[buf][k][ty * 4];
            float4 a1 = *(const float4*)&As[buf][k][ty * 4 + 64];
            float4 b0 = *(const float4*)&Bs[buf][k][tx * 4];
            float4 b1 = *(const float4*)&Bs[buf][k][tx * 4 + 64];
            float a[8] = {a0.x, a0.y, a0.z, a0.w, a1.x, a1.y, a1.z, a1.w};
            float b[8] = {b0.x, b0.y, b0.z, b0.w, b1.x, b1.y, b1.z, b1.w};
#pragma unroll
            for (int i = 0; i < 8; i++)
#pragma unroll
                for (int j = 0; j < 8; j++) acc[i][j] += a[i] * b[j];
        }
        if (kt + 1 < KT) {
            GEMM_STS(buf ^ 1);
            __syncthreads();
        }
        buf ^= 1;
    }

    float gte = 0.0f;
    if (MODE == 5) gte = 1.0f / (1.0f + expf(-ex2[0]));
#pragma unroll
    for (int i = 0; i < 8; i++) {
        int m = m0 + ty * 4 + (i < 4 ? i : 60 + i);
#pragma unroll
        for (int j = 0; j < 8; j++) {
            int n = n0 + tx * 4 + (j < 4 ? j : 60 + j);
            if (n >= N) continue;
            float v = acc[i][j];
            if (MODE == 3) {
                float y = 1.0f / (1.0f + expf(-(v + bias[n])));
                C[(size_t)m * LITDIM + n]          = logf(fmaxf(y, 1e-6f));
                C[(size_t)m * LITDIM + HIDDIM + n] = logf(fmaxf(1.0f - y, 1e-6f));
            } else if (MODE == 4) {
                C[(size_t)m * ldc + n] = expf(v);
            } else if (MODE == 5) {
                float s = 1.0f / (1.0f + expf(-v));
                C[(size_t)m * ldc + n] = ex1[(size_t)m * CDIM + n] + gte * v + (1.0f - gte) * s;
            }
        }
    }
#undef GEMM_LOAD
#undef GEMM_STS
}

// ---------------- windowed attention, TENSOR-CORE (R12 form, 41KB smem) ------
// grid (NWIN, 3), block 128 (4 warps). Per block: one (window, head).
// Scores: S(64x56, valid 49x49) = Q(64x32) @ K^T via m16n8k8 3xTF32.
// AV:     O(64x32) = P(64x56) @ V via m16n8k8 3xTF32, V stored transposed.
// Padding: q rows 49..63 zero, k rows 49..55 zero, vsT cols 49..55 zero,
// ps cols 49..55 zeroed during softmax -> no NaN reaches valid outputs.
__global__ __launch_bounds__(128) void attn3_kernel(
    const float* __restrict__ qkv, float* __restrict__ ao)
{
    __shared__ __align__(16) float qs[64][36];   // pitch 36: frag loads conflict-free
    __shared__ __align__(16) float ks[56][36];
    __shared__ float vsT[32][60];                // V transposed: vsT[d][t]
    __shared__ float ps[64][60];
    __shared__ int ltab[49];
    __shared__ int otab[49];

    int w  = blockIdx.x;
    int h  = blockIdx.y;
    int b  = w >> 6;
    int wh = (w >> 3) & 7;
    int ww = w & 7;
    int tid  = threadIdx.x;
    int warp = tid >> 5;
    int lane = tid & 31;
    int gid  = lane >> 2;     // 0..7
    int tig  = lane & 3;      // 0..3

    if (tid < 49) {
        int th = tid / 7, tw = tid % 7;
        int r = (wh * 7 + th + 3) % IMGHW;
        int c = (ww * 7 + tw + 3) % IMGHW;
        ltab[tid] = b * (IMGHW * IMGHW) + r * IMGHW + c;
        int ro = wh * 7 + (th + 3) % 7;          // intra-window inverse roll
        int co = ww * 7 + (tw + 3) % 7;
        otab[tid] = b * (IMGHW * IMGHW) + ro * IMGHW + co;
    }
    // zero pads
    for (int i = tid; i < 15 * 36; i += 128) qs[49 + i / 36][i % 36] = 0.0f;
    for (int i = tid; i < 7 * 36; i += 128)  ks[49 + i / 36][i % 36] = 0.0f;
    for (int i = tid; i < 32 * 11; i += 128) vsT[i / 11][49 + i % 11] = 0.0f;
    __syncthreads();

    // load q/k rows; v transposed
    for (int i = tid; i < 49 * 8; i += 128) {
        int t = i >> 3, dq = (i & 7) * 4;
        const float* base = qkv + (size_t)ltab[t] * QKVDIM + h * 32 + dq;
        *(float4*)&qs[t][dq] = *(const float4*)base;
        *(float4*)&ks[t][dq] = *(const float4*)(base + 96);
        float4 v = *(const float4*)(base + 192);
        vsT[dq][t]     = v.x;
        vsT[dq + 1][t] = v.y;
        vsT[dq + 2][t] = v.z;
        vsT[dq + 3][t] = v.w;
    }
    __syncthreads();

    const float scale = 0.17677669529663687f;  // 1/sqrt(32)

    // ---- scores: warp = m-tile (16 rows); 7 n-tiles x 4 k-tiles x 3 mma ----
    {
        int mrow = warp * 16 + gid;
        unsigned ah[4][4], al[4][4];
#pragma unroll
        for (int kt = 0; kt < 4; kt++) {
            int kc = kt * 8 + tig;
            float a0 = qs[mrow][kc];
            float a1 = qs[mrow + 8][kc];
            float a2 = qs[mrow][kc + 4];
            float a3 = qs[mrow + 8][kc + 4];
            SPLIT2(ah[kt][0], al[kt][0], a0);
            SPLIT2(ah[kt][1], al[kt][1], a1);
            SPLIT2(ah[kt][2], al[kt][2], a2);
            SPLIT2(ah[kt][3], al[kt][3], a3);
        }
#pragma unroll
        for (int nt = 0; nt < 7; nt++) {
            unsigned bh[4][2], bl[4][2];
#pragma unroll
            for (int kt = 0; kt < 4; kt++) {
                int kc = kt * 8 + tig;
                float b0 = ks[nt * 8 + gid][kc];
                float b1 = ks[nt * 8 + gid][kc + 4];
                SPLIT2(bh[kt][0], bl[kt][0], b0);
                SPLIT2(bh[kt][1], bl[kt][1], b1);
            }
            float acc[4] = {0.0f, 0.0f, 0.0f, 0.0f};
#pragma unroll
            for (int kt = 0; kt < 4; kt++) {
                mma_tf32(acc, ah[kt], bh[kt]);
                mma_tf32(acc, al[kt], bh[kt]);
                mma_tf32(acc, ah[kt], bl[kt]);
            }
            int c = nt * 8 + tig * 2;
            if (c < 49) {
                ps[mrow][c]     = acc[0] * scale;
                ps[mrow + 8][c] = acc[2] * scale;
            }
            if (c + 1 < 49) {
                ps[mrow][c + 1]     = acc[1] * scale;
                ps[mrow + 8][c + 1] = acc[3] * scale;
            }
        }
    }
    __syncthreads();

    // softmax: 2 threads per row (rows 0..48); also zero pad cols 49..55
    if (tid < 98) {
        int row = tid >> 1, half = tid & 1;
        int c0 = half ? 25 : 0;
        int c1 = half ? 49 : 25;
        unsigned mask = (tid < 96) ? 0xffffffffu : 0x3u;
        float mx = -1e30f;
        for (int j = c0; j < c1; j++) mx = fmaxf(mx, ps[row][j]);
        mx = fmaxf(mx, __shfl_xor_sync(mask, mx, 1));
        float sum = 0.0f;
        for (int j = c0; j < c1; j++) {
            float e = expf(ps[row][j] - mx);
            ps[row][j] = e;
            sum += e;
        }
        sum += __shfl_xor_sync(mask, sum, 1);
        float inv = 1.0f / sum;
        for (int j = c0; j < c1; j++) ps[row][j] *= inv;
        if (half) {
#pragma unroll
            for (int j = 49; j < 56; j++) ps[row][j] = 0.0f;
        }
    }
    __syncthreads();

    // ---- AV: O(64x32) = P @ V; warp = m-tile; 4 n-tiles x 7 k-tiles x 3 ----
    {
        int mrow = warp * 16 + gid;
        unsigned ah[7][4], al[7][4];
#pragma unroll
        for (int kt = 0; kt < 7; kt++) {
            int kc = kt * 8 + tig;
            float a0 = ps[mrow][kc];
            float a1 = ps[mrow + 8][kc];
            float a2 = ps[mrow][kc + 4];
            float a3 = ps[mrow + 8][kc + 4];
            SPLIT2(ah[kt][0], al[kt][0], a0);
            SPLIT2(ah[kt][1], al[kt][1], a1);
            SPLIT2(ah[kt][2], al[kt][2], a2);
            SPLIT2(ah[kt][3], al[kt][3], a3);
        }
#pragma unroll
        for (int nt = 0; nt < 4; nt++) {
            unsigned bh[7][2], bl[7][2];
#pragma unroll
            for (int kt = 0; kt < 7; kt++) {
                int kc = kt * 8 + tig;
                float b0 = vsT[nt * 8 + gid][kc];
                float b1 = vsT[nt * 8 + gid][kc + 4];
                SPLIT2(bh[kt][0], bl[kt][0], b0);
                SPLIT2(bh[kt][1], bl[kt][1], b1);
            }
            float acc[4] = {0.0f, 0.0f, 0.0f, 0.0f};
#pragma unroll
            for (int kt = 0; kt < 7; kt++) {
                mma_tf32(acc, ah[kt], bh[kt]);
                mma_tf32(acc, al[kt], bh[kt]);
                mma_tf32(acc, ah[kt], bl[kt]);
            }
            int d = nt * 8 + tig * 2;
            int t0 = mrow, t1 = mrow + 8;
            if (t0 < 49) {
                float2 o = {acc[0], acc[1]};
                *(float2*)&ao[(size_t)otab[t0] * CDIM + h * 32 + d] = o;
            }
            if (t1 < 49) {
                float2 o = {acc[2], acc[3]};
                *(float2*)&ao[(size_t)otab[t1] * CDIM + h * 32 + d] = o;
            }
        }
    }
}

// ---------------- host launcher ----------------------------------------------
extern "C" void kernel_launch(void* const* d_in, const int* in_sizes, int n_in,
                              void* d_out, int out_size)
{
    const float* x       = (const float*)d_in[0];
    const float* n1g     = (const float*)d_in[1];
    const float* n1b     = (const float*)d_in[2];
    const float* qkv_w   = (const float*)d_in[3];
    const float* qkv_b   = (const float*)d_in[4];
    const float* proj_w  = (const float*)d_in[5];
    const float* proj_b  = (const float*)d_in[6];
    const float* n2g     = (const float*)d_in[7];
    const float* n2b     = (const float*)d_in[8];
    const float* fng     = (const float*)d_in[9];
    const float* fnb     = (const float*)d_in[10];
    const float* pin_w   = (const float*)d_in[11];
    const float* pin_b   = (const float*)d_in[12];
    const float* tm_inc  = (const float*)d_in[13];
    const float* tm_out  = (const float*)d_in[14];
    const float* gate    = (const float*)d_in[15];
    float* out           = (float*)d_out;

    float *p_qkv, *p_ao, *p_x1, *p_w, *p_ll, *p_cl;
    int* p_skip;
    cudaGetSymbolAddress((void**)&p_qkv, g_qkv);
    cudaGetSymbolAddress((void**)&p_ao,  g_ao);
    cudaGetSymbolAddress((void**)&p_x1,  g_x1);
    cudaGetSymbolAddress((void**)&p_w,   g_w);
    cudaGetSymbolAddress((void**)&p_ll,  g_ll);
    cudaGetSymbolAddress((void**)&p_cl,  g_cl);
    cudaGetSymbolAddress((void**)&p_skip, g_skip);

    // opt-in dynamic smem (>48KB); idempotent host-side attr, not captured
    static bool attr_done = false;
    if (!attr_done) {
        cudaFuncSetAttribute(gemmtc_k<1, true>,
                             cudaFuncAttributeMaxDynamicSharedMemorySize, TC_SMEM);
        cudaFuncSetAttribute(gemmtc_k<2, false>,
                             cudaFuncAttributeMaxDynamicSharedMemorySize, TC_SMEM);
        attr_done = true;
    }

    const int MB = NTOK / 128;  // 392

    // 0) guard: decide whether the clause branch is provably negligible
    guard_kernel<<<1, 1024>>>(tm_inc, tm_out, p_skip);

    // 1) QKV GEMM (tensor cores, 3xTF32, BM=128) with LN1 fully fused in-load
    gemmtc_k<1, true><<<dim3(MB, QKVDIM / 96), 256, TC_SMEM>>>(
        x, qkv_w, qkv_b, nullptr, p_qkv, QKVDIM,
        n1g, n1b, nullptr, nullptr, p_skip);

    // 2) windowed attention: tensor cores, one block per (window, head)
    attn3_kernel<<<dim3(NWIN, 3), 128>>>(p_qkv, p_ao);

    // 3) proj + residual (tensor cores); fast path writes final output
    gemmtc_k<2, false><<<dim3(MB, 1), 256, TC_SMEM>>>(
        p_ao, proj_w, proj_b, x, p_x1, CDIM,
        nullptr, nullptr, out, gate, p_skip);

    // 4) double layernorm -> g_w   (skipped on fast path)
    ln2_kernel<<<NTOK / 8, 256>>>(p_x1, n2g, n2b, fng, fnb, p_w, p_skip);

    // 5) pin GEMM + sigmoid + log-literals -> g_ll   (skipped on fast path)
    gemm2_k<3, false, false, 1><<<dim3(MB, (HIDDIM + 127) / 128), 256>>>(
        p_w, pin_w, pin_b, nullptr, nullptr, p_ll,
        NTOK, HIDDIM, CDIM, LITDIM, p_skip);

    // 6) clause GEMM, binary mask, exp epilogue -> g_cl (skipped on fast path)
    gemm2_k<4, false, true, 1><<<dim3(MB, 1), 256>>>(
        p_ll, tm_inc, nullptr, nullptr, nullptr, p_cl,
        NTOK, NCLAUSE, LITDIM, NCLAUSE, p_skip);

    // 7) final GEMM: full path only (fast path already wrote out in step 3)
    gemm2_k<5, true, false, 1><<<dim3(MB, 1), 256>>>(
        p_cl, tm_out, nullptr, p_x1, gate, out,
        NTOK, CDIM, NCLAUSE, CDIM, p_skip);

    (void)in_sizes; (void)n_in; (void)out_size;
}